// round 6
// baseline (speedup 1.0000x reference)
#include <cuda_runtime.h>
#include <cstdint>

#define BB 64
#define NN 512
#define NROWS (BB*NN)            /* 32768 */
#define BNS  0.9995003746f       /* 1/sqrt(1+1e-3) */
#define EXC  (-14.4269504089f)   /* -10*log2(e) */
#define IEXC (-0.0693147180560f) /* 1/EXC */
#define L2E  1.4426950409f

/* ---------------- scratch: __device__ globals ---------------------------- */
__device__ float g_feat0[NROWS * 64];
__device__ float g_feat1[NROWS * 64];
__device__ float g_mask[NROWS];
__device__ float g_S[2 * NROWS];
__device__ float g_T[2 * NROWS];
__device__ int   g_len[BB];
__device__ float g_part[256 * 64 * 128];
__device__ float g_h0[64 * 128];

/* ---------------- helpers ------------------------------------------------- */
__device__ __forceinline__ float ex2(float x) {
    float r; asm("ex2.approx.ftz.f32 %0, %1;" : "=f"(r) : "f"(x)); return r;
}
__device__ __forceinline__ float rcpf(float x) {
    float r; asm("rcp.approx.ftz.f32 %0, %1;" : "=f"(r) : "f"(x)); return r;
}
__device__ __forceinline__ float tanh_fast(float x) {
    float e = ex2(x * (2.f * L2E));
    return fmaf(-2.f, rcpf(e + 1.f), 1.f);
}
__device__ __forceinline__ float sigmoid_fast(float x) {
    return rcpf(1.f + ex2(-L2E * x));
}
__device__ __forceinline__ unsigned long long ffma2(unsigned long long a,
                                                    unsigned long long b,
                                                    unsigned long long c) {
    unsigned long long d;
    asm("fma.rn.f32x2 %0, %1, %2, %3;" : "=l"(d) : "l"(a), "l"(b), "l"(c));
    return d;
}
__device__ __forceinline__ unsigned long long pack2(float x, float y) {
    unsigned long long d;
    asm("mov.b64 %0, {%1, %2};" : "=l"(d) : "f"(x), "f"(y));
    return d;
}
__device__ __forceinline__ float2 unpack2(unsigned long long v) {
    float2 r;
    asm("mov.b64 {%0, %1}, %2;" : "=f"(r.x), "=f"(r.y) : "l"(v));
    return r;
}

/* ---------------- prep: embeddings + feature concat + mask --------------- */
__global__ void prep_kernel(const float* __restrict__ xx,
                            const float* __restrict__ e1,
                            const float* __restrict__ e2,
                            const float* __restrict__ e3) {
    int row = blockIdx.x * 256 + threadIdx.x;
    if (row >= NROWS) return;
    const float* xr = xx + (size_t)row * 30;
    float* fr = g_feat0 + (size_t)row * 64;
    g_mask[row] = xr[0];
    int i1 = (int)fabsf(xr[27]);
    int i2 = (int)fabsf(xr[28]);
    int i3 = (int)fabsf(xr[29]);
    fr[0] = e1[2 * i1];  fr[1] = e1[2 * i1 + 1];
    fr[2] = e2[2 * i2];  fr[3] = e2[2 * i2 + 1];
    fr[4] = e3[2 * i3];  fr[5] = e3[2 * i3 + 1];
#pragma unroll
    for (int c = 0; c < 27; c++) fr[6 + c] = xr[c];
}

/* ---------------- per-batch valid length (mask is a 1/0 prefix) ---------- */
__global__ void len_kernel() {
    __shared__ float red[256];
    int b = blockIdx.x, tid = threadIdx.x;
    red[tid] = g_mask[b * NN + tid] + g_mask[b * NN + 256 + tid];
    __syncthreads();
    for (int o = 128; o > 0; o >>= 1) {
        if (tid < o) red[tid] += red[tid + o];
        __syncthreads();
    }
    if (tid == 0) g_len[b] = (int)(red[0] + 0.5f);
}

/* ---------------- pairwise S/T kernel (dot-product form) ------------------ */
template <int ND, int FULLI>
__global__ void pair_kernel(int bufIn, int col0) {
    __shared__ float4 cs4[256];
    __shared__ float  Ps[256];
    const float* feat = bufIn ? g_feat1 : g_feat0;
    int b = blockIdx.z;
    int L = g_len[b];
    int jbase = blockIdx.x * 128;
    if (jbase >= L) return;
    int ib = blockIdx.y;
    int lo = ib * 256;
    int tid = threadIdx.x;
    const float* fb = feat + (size_t)b * NN * 64;

    for (int r = tid; r < 256; r += 128) {
        const float* rowp = fb + (size_t)(lo + r) * 64 + col0;
        float c0, c1, c2 = 0.f, c3 = 0.f;
        if (ND == 4) {
            float4 v = *(const float4*)rowp;
            c0 = v.x; c1 = v.y; c2 = v.z; c3 = v.w;
        } else {
            c0 = rowp[0]; c1 = rowp[1];
        }
        cs4[r] = make_float4(c0, c1, c2, c3);
        Ps[r] = EXC * (c0 * c0 + c1 * c1 + c2 * c2 + c3 * c3);
    }
    __syncthreads();

    int j = jbase + tid;
    const float* jr = fb + (size_t)j * 64 + col0;
    float cj0, cj1, cj2 = 0.f, cj3 = 0.f;
    if (ND == 4) {
        float4 v = *(const float4*)jr;
        cj0 = v.x; cj1 = v.y; cj2 = v.z; cj3 = v.w;
    } else {
        cj0 = jr[0]; cj1 = jr[1];
    }
    float Qj = EXC * (cj0 * cj0 + cj1 * cj1 + cj2 * cj2 + cj3 * cj3);
    float m0 = -2.f * EXC * cj0, m1 = -2.f * EXC * cj1;
    float m2 = -2.f * EXC * cj2, m3 = -2.f * EXC * cj3;

    int L4u = FULLI ? NN : min(NN, (L + 3) & ~3);
    int hi = max(lo, min(lo + 256, L4u));
    int cnt = hi - lo;                   /* multiple of 4 */
    int mult = FULLI ? 0 : (lo + 256) - hi;

    float S0 = 0.f, S1 = 0.f, S2 = 0.f, S3 = 0.f;
    float U0 = 0.f, U1 = 0.f, U2 = 0.f, U3 = 0.f;
    for (int i = 0; i < cnt; i += 4) {
#pragma unroll
        for (int u = 0; u < 4; u++) {
            float4 c = cs4[i + u];
            float t = Ps[i + u];
            t = fmaf(c.x, m0, t);
            t = fmaf(c.y, m1, t);
            if (ND == 4) {
                t = fmaf(c.z, m2, t);
                t = fmaf(c.w, m3, t);
            }
            float arg = t + Qj;
            float w = ex2(arg);
            if (u == 0)      { S0 += w; U0 = fmaf(arg, w, U0); }
            else if (u == 1) { S1 += w; U1 = fmaf(arg, w, U1); }
            else if (u == 2) { S2 += w; U2 = fmaf(arg, w, U2); }
            else             { S3 += w; U3 = fmaf(arg, w, U3); }
        }
    }
    if (!FULLI && mult > 0) {
        /* row 511 is guaranteed invalid whenever mult > 0 */
        const float* vr = fb + (size_t)(NN - 1) * 64 + col0;
        float v0 = vr[0], v1 = vr[1];
        float v2 = (ND == 4) ? vr[2] : 0.f, v3 = (ND == 4) ? vr[3] : 0.f;
        float t = EXC * (v0 * v0 + v1 * v1 + v2 * v2 + v3 * v3);
        t = fmaf(v0, m0, t); t = fmaf(v1, m1, t);
        if (ND == 4) { t = fmaf(v2, m2, t); t = fmaf(v3, m3, t); }
        float arg = t + Qj;
        float w = ex2(arg);
        float fm = (float)mult;
        S0 = fmaf(fm, w, S0);
        U0 = fmaf(fm * arg, w, U0);
    }
    int o = ib * NROWS + b * NN + j;
    g_S[o] = (S0 + S1) + (S2 + S3);
    g_T[o] = ((U0 + U1) + (U2 + U3)) * IEXC;
}

/* ---------------- GNN layer: pipelined pack-free f32x2 GEMM --------------
 * As interleaved (col 2k = A1_k, col 2k+1 = A2_k); x duplicated (x,x) in
 * smem. Manual 1-iter software pipeline over fully unrolled Din loop
 * (padding row keeps the last prefetch in-bounds). Per-row epilogue coeffs
 * (msm1, mt, m) are precomputed into smem during the prologue so the
 * epilogue has no global loads.
 */
template <int Din>
__global__ void __launch_bounds__(256)
layer_kernel(int bufIn, int bufOut,
             const float* __restrict__ A,
             const float* __restrict__ bvec,
             const float* __restrict__ gamma,
             const float* __restrict__ beta) {
    constexpr int DP = (Din + 3) & ~3;
    __shared__ __align__(16) float As[Din + 1][128];
    __shared__ __align__(16) unsigned long long xd[DP + 1][32];
    __shared__ __align__(16) float4 coef[32];
    const float* featIn = bufIn ? g_feat1 : g_feat0;
    float* featOut = bufOut ? g_feat1 : g_feat0;
    int tid = threadIdx.x;
    int row0 = blockIdx.x * 32;
    int b = row0 >> 9;
    int L = g_len[b];
    int tx = tid & 31, ty = tid >> 5;
    int k0 = tx * 2;

    if ((row0 & (NN - 1)) >= L) {    /* all 32 rows invalid: out = tanh(beta) */
        float2 v = make_float2(tanh_fast(beta[k0]), tanh_fast(beta[k0 + 1]));
        for (int r = ty; r < 32; r += 8)
            *(float2*)&featOut[(size_t)(row0 + r) * 64 + k0] = v;
        return;
    }

    /* per-row epilogue coefficients (LDG latency hidden by the barrier) */
    if (tid < 32) {
        int row = row0 + tid;
        float m = g_mask[row];
        float S = g_S[row] + g_S[NROWS + row];
        float T = g_T[row] + g_T[NROWS + row];
        coef[tid] = make_float4(fmaf(m, S, -1.f), m * T, m, 0.f);
    }
    for (int idx = tid; idx < Din * 64; idx += 256) {
        int d = idx >> 6, k = idx & 63;
        As[d][2 * k]     = A[d * 64 + k];
        As[d][2 * k + 1] = A[(Din + d) * 64 + k];
    }
    for (int idx = tid; idx < 32 * (DP / 4); idx += 256) {
        int r = idx & 31, dq = idx >> 5;
        float4 v = *(const float4*)&featIn[(size_t)(row0 + r) * 64 + dq * 4];
        xd[dq * 4 + 0][r] = pack2(v.x, v.x);
        xd[dq * 4 + 1][r] = pack2(v.y, v.y);
        xd[dq * 4 + 2][r] = pack2(v.z, v.z);
        xd[dq * 4 + 3][r] = pack2(v.w, v.w);
    }
    __syncthreads();

    unsigned long long acc00 = 0, acc01 = 0, acc10 = 0, acc11 = 0;
    unsigned long long acc20 = 0, acc21 = 0, acc30 = 0, acc31 = 0;

    ulonglong2 ap = *(const ulonglong2*)&As[0][tx * 4];
    ulonglong2 xa = *(const ulonglong2*)&xd[0][ty * 4];
    ulonglong2 xb = *(const ulonglong2*)&xd[0][ty * 4 + 2];
#pragma unroll
    for (int d = 0; d < Din; d++) {
        /* prefetch next iter (pad row makes d+1 always in-bounds) */
        ulonglong2 apn = *(const ulonglong2*)&As[d + 1][tx * 4];
        ulonglong2 xan = *(const ulonglong2*)&xd[d + 1][ty * 4];
        ulonglong2 xbn = *(const ulonglong2*)&xd[d + 1][ty * 4 + 2];
        acc00 = ffma2(xa.x, ap.x, acc00);
        acc01 = ffma2(xa.x, ap.y, acc01);
        acc10 = ffma2(xa.y, ap.x, acc10);
        acc11 = ffma2(xa.y, ap.y, acc11);
        acc20 = ffma2(xb.x, ap.x, acc20);
        acc21 = ffma2(xb.x, ap.y, acc21);
        acc30 = ffma2(xb.y, ap.x, acc30);
        acc31 = ffma2(xb.y, ap.y, acc31);
        ap = apn; xa = xan; xb = xbn;
    }

    float a30 = A[2 * Din * 64 + k0], a31 = A[2 * Din * 64 + k0 + 1];
    float bb0 = bvec[k0], bb1 = bvec[k0 + 1];
    float g0 = gamma[k0] * BNS, g1 = gamma[k0 + 1] * BNS;
    float be0 = beta[k0], be1 = beta[k0 + 1];

    unsigned long long a0[4] = {acc00, acc10, acc20, acc30};
    unsigned long long a1[4] = {acc01, acc11, acc21, acc31};
#pragma unroll
    for (int r = 0; r < 4; r++) {
        int row = row0 + ty * 4 + r;
        float4 cf = coef[ty * 4 + r];        /* (msm1, mt, m) broadcast LDS */
        float2 uv0 = unpack2(a0[r]);
        float2 uv1 = unpack2(a1[r]);
        float val0 = (fmaf(cf.x, uv0.y, uv0.x) + fmaf(cf.y, a30, bb0)) * cf.z;
        float val1 = (fmaf(cf.x, uv1.y, uv1.x) + fmaf(cf.y, a31, bb1)) * cf.z;
        *(float2*)&featOut[(size_t)row * 64 + k0] =
            make_float2(tanh_fast(fmaf(g0, val0, be0)),
                        tanh_fast(fmaf(g1, val1, be1)));
    }
}

/* ---------------- dense head --------------------------------------------- */
/* split-K partial: x(64,32768)@dW0(32768,128); 256 blocks x K-slab 128. */
__global__ void dense0_partial(const float* __restrict__ dW0) {
    __shared__ float xsT[128][68];   /* [kk][m], padded */
    int tid = threadIdx.x;           /* 128 */
    int k0 = blockIdx.x * 128;
    for (int idx = tid; idx < 128 * 64; idx += 128) {
        int kk = idx & 127, m = idx >> 7;
        xsT[kk][m] = g_feat1[(size_t)m * 32768 + k0 + kk];
    }
    __syncthreads();
    int n = tid;
    unsigned long long acc[32];
#pragma unroll
    for (int mp = 0; mp < 32; mp++) acc[mp] = 0ull;
#pragma unroll 2
    for (int kk = 0; kk < 128; kk++) {
        float w = dW0[(size_t)(k0 + kk) * 128 + n];
        unsigned long long wd = pack2(w, w);
        const float* xr = &xsT[kk][0];
#pragma unroll
        for (int mq = 0; mq < 16; mq++) {
            ulonglong2 xp = *(const ulonglong2*)&xr[mq * 4];
            acc[2 * mq]     = ffma2(xp.x, wd, acc[2 * mq]);
            acc[2 * mq + 1] = ffma2(xp.y, wd, acc[2 * mq + 1]);
        }
    }
    float* p = g_part + (size_t)blockIdx.x * 8192;
#pragma unroll
    for (int mp = 0; mp < 32; mp++) {
        float2 v = unpack2(acc[mp]);
        p[(2 * mp) * 128 + n] = v.x;
        p[(2 * mp + 1) * 128 + n] = v.y;
    }
}

/* deterministic fixed-order reduce + bias + bn + sigmoid (MLP via unroll) */
__global__ void dense0_reduce(const float* __restrict__ db0,
                              const float* __restrict__ dg,
                              const float* __restrict__ dbt) {
    int idx = blockIdx.x * 256 + threadIdx.x;   /* 8192 */
    float s = 0.f;
#pragma unroll 16
    for (int p = 0; p < 256; p++) s += g_part[(size_t)p * 8192 + idx];
    int n = idx & 127;
    float v = s + db0[n];
    v = fmaf(dg[n] * BNS, v, dbt[n]);
    g_h0[idx] = sigmoid_fast(v);
}

/* h0(64,128)@dW1(128,128) -> sigmoid(bn) -> @W2(128,2)+b2 -> out(64,4) */
__global__ void head_kernel(const float* __restrict__ dW1,
                            const float* __restrict__ db1,
                            const float* __restrict__ dg,
                            const float* __restrict__ dbt,
                            const float* __restrict__ W2,
                            const float* __restrict__ b2,
                            float* __restrict__ out) {
    __shared__ float h0[64][128];
    __shared__ float h1[16][128];
    int tid = threadIdx.x;           /* 128 */
    int m0 = blockIdx.x * 16;
    for (int idx = tid; idx < 8192; idx += 128)
        h0[idx >> 7][idx & 127] = g_h0[idx];
    __syncthreads();
    int n = tid;
    float acc[16];
#pragma unroll
    for (int m = 0; m < 16; m++) acc[m] = db1[n];
    for (int k = 0; k < 128; k++) {
        float w = dW1[k * 128 + n];
#pragma unroll
        for (int m = 0; m < 16; m++) acc[m] = fmaf(h0[m0 + m][k], w, acc[m]);
    }
    float g = dg[128 + n] * BNS, bt = dbt[128 + n];
#pragma unroll
    for (int m = 0; m < 16; m++)
        h1[m][n] = sigmoid_fast(fmaf(g, acc[m], bt));
    __syncthreads();
    if (tid < 16) {
        int m = tid;
        float o0 = b2[0], o1 = b2[1];
        for (int nn = 0; nn < 128; nn++) {
            float h = h1[m][nn];
            o0 = fmaf(h, W2[2 * nn], o0);
            o1 = fmaf(h, W2[2 * nn + 1], o1);
        }
        out[(m0 + m) * 4 + 0] = o0;
        out[(m0 + m) * 4 + 1] = o1;
        out[(m0 + m) * 4 + 2] = 0.f;
        out[(m0 + m) * 4 + 3] = 0.f;
    }
}

/* ---------------- launch -------------------------------------------------- */
extern "C" void kernel_launch(void* const* d_in, const int* in_sizes, int n_in,
                              void* d_out, int out_size) {
    const float* xx        = (const float*)d_in[0];
    const float* emb1      = (const float*)d_in[1];
    const float* emb2      = (const float*)d_in[2];
    const float* emb3      = (const float*)d_in[3];
    const float* A0        = (const float*)d_in[4];
    const float* b0        = (const float*)d_in[5];
    const float* A_rest    = (const float*)d_in[6];
    const float* b_rest    = (const float*)d_in[7];
    const float* bn_gamma  = (const float*)d_in[8];
    const float* bn_beta   = (const float*)d_in[9];
    const float* dW0       = (const float*)d_in[10];
    const float* db0       = (const float*)d_in[11];
    const float* dW1       = (const float*)d_in[12];
    const float* db1       = (const float*)d_in[13];
    const float* dbn_gamma = (const float*)d_in[14];
    const float* dbn_beta  = (const float*)d_in[15];
    const float* W2        = (const float*)d_in[16];
    const float* b2        = (const float*)d_in[17];
    float* out = (float*)d_out;

    prep_kernel<<<NROWS / 256, 256>>>(xx, emb1, emb2, emb3);
    len_kernel<<<BB, 256>>>();

    /* layer 0: Din=33, c = cols 31..32, full i-range (c from raw xx) */
    pair_kernel<2, 1><<<dim3(4, 2, BB), 128>>>(0, 31);
    layer_kernel<33><<<NROWS / 32, 256>>>(0, 1, A0, b0, bn_gamma, bn_beta);

    /* layers 1..4: Din=64, c = cols 60..63; ping-pong */
    for (int l = 1; l < 5; l++) {
        int in = l & 1;
        int outb = in ^ 1;
        pair_kernel<4, 0><<<dim3(4, 2, BB), 128>>>(in, 60);
        layer_kernel<64><<<NROWS / 32, 256>>>(in, outb,
                                          A_rest + (size_t)(l - 1) * 129 * 64,
                                          b_rest + (size_t)(l - 1) * 64,
                                          bn_gamma + (size_t)l * 64,
                                          bn_beta + (size_t)l * 64);
    }

    dense0_partial<<<256, 128>>>(dW0);
    dense0_reduce<<<32, 256>>>(db0, dbn_gamma, dbn_beta);
    head_kernel<<<4, 128>>>(dW1, db1, dbn_gamma, dbn_beta, W2, b2, out);
}

// round 9
// speedup vs baseline: 1.3333x; 1.3333x over previous
#include <cuda_runtime.h>
#include <cstdint>

#define BB 64
#define NN 512
#define NROWS (BB*NN)            /* 32768 */
#define BNS  0.9995003746f       /* 1/sqrt(1+1e-3) */
#define EXC  (-14.4269504089f)   /* -10*log2(e) */
#define IEXC (-0.0693147180560f) /* 1/EXC */
#define L2E  1.4426950409f

/* ---------------- scratch: __device__ globals ---------------------------- */
__device__ float g_feat0[NROWS * 64];
__device__ float g_feat1[NROWS * 64];
__device__ float g_mask[NROWS];
__device__ float g_S[2 * NROWS];
__device__ float g_T[2 * NROWS];
__device__ int   g_len[BB];
__device__ float g_part[256 * 64 * 128];
__device__ float g_h0[64 * 128];

/* ---------------- helpers ------------------------------------------------- */
__device__ __forceinline__ float ex2(float x) {
    float r; asm("ex2.approx.ftz.f32 %0, %1;" : "=f"(r) : "f"(x)); return r;
}
__device__ __forceinline__ float rcpf(float x) {
    float r; asm("rcp.approx.ftz.f32 %0, %1;" : "=f"(r) : "f"(x)); return r;
}
__device__ __forceinline__ float tanh_fast(float x) {
    float e = ex2(x * (2.f * L2E));
    return fmaf(-2.f, rcpf(e + 1.f), 1.f);
}
__device__ __forceinline__ float sigmoid_fast(float x) {
    return rcpf(1.f + ex2(-L2E * x));
}
__device__ __forceinline__ unsigned long long ffma2(unsigned long long a,
                                                    unsigned long long b,
                                                    unsigned long long c) {
    unsigned long long d;
    asm("fma.rn.f32x2 %0, %1, %2, %3;" : "=l"(d) : "l"(a), "l"(b), "l"(c));
    return d;
}
__device__ __forceinline__ unsigned long long pack2(float x, float y) {
    unsigned long long d;
    asm("mov.b64 %0, {%1, %2};" : "=l"(d) : "f"(x), "f"(y));
    return d;
}
__device__ __forceinline__ float2 unpack2(unsigned long long v) {
    float2 r;
    asm("mov.b64 {%0, %1}, %2;" : "=f"(r.x), "=f"(r.y) : "l"(v));
    return r;
}

/* ---------------- prep: embeddings + feature concat + mask --------------- */
__global__ void prep_kernel(const float* __restrict__ xx,
                            const float* __restrict__ e1,
                            const float* __restrict__ e2,
                            const float* __restrict__ e3) {
    int row = blockIdx.x * 256 + threadIdx.x;
    if (row >= NROWS) return;
    const float* xr = xx + (size_t)row * 30;
    float* fr = g_feat0 + (size_t)row * 64;
    g_mask[row] = xr[0];
    int i1 = (int)fabsf(xr[27]);
    int i2 = (int)fabsf(xr[28]);
    int i3 = (int)fabsf(xr[29]);
    fr[0] = e1[2 * i1];  fr[1] = e1[2 * i1 + 1];
    fr[2] = e2[2 * i2];  fr[3] = e2[2 * i2 + 1];
    fr[4] = e3[2 * i3];  fr[5] = e3[2 * i3 + 1];
#pragma unroll
    for (int c = 0; c < 27; c++) fr[6 + c] = xr[c];
}

/* ---------------- per-batch valid length (mask is a 1/0 prefix) ---------- */
__global__ void len_kernel() {
    __shared__ float red[256];
    int b = blockIdx.x, tid = threadIdx.x;
    red[tid] = g_mask[b * NN + tid] + g_mask[b * NN + 256 + tid];
    __syncthreads();
    for (int o = 128; o > 0; o >>= 1) {
        if (tid < o) red[tid] += red[tid + o];
        __syncthreads();
    }
    if (tid == 0) g_len[b] = (int)(red[0] + 0.5f);
}

/* ---------------- pairwise S/T kernel (dot-product form) ------------------ */
template <int ND, int FULLI>
__global__ void pair_kernel(int bufIn, int col0) {
    __shared__ float4 cs4[256];
    __shared__ float  Ps[256];
    const float* feat = bufIn ? g_feat1 : g_feat0;
    int b = blockIdx.z;
    int L = g_len[b];
    int jbase = blockIdx.x * 128;
    if (jbase >= L) return;
    int ib = blockIdx.y;
    int lo = ib * 256;
    int tid = threadIdx.x;
    const float* fb = feat + (size_t)b * NN * 64;

    for (int r = tid; r < 256; r += 128) {
        const float* rowp = fb + (size_t)(lo + r) * 64 + col0;
        float c0, c1, c2 = 0.f, c3 = 0.f;
        if (ND == 4) {
            float4 v = *(const float4*)rowp;
            c0 = v.x; c1 = v.y; c2 = v.z; c3 = v.w;
        } else {
            c0 = rowp[0]; c1 = rowp[1];
        }
        cs4[r] = make_float4(c0, c1, c2, c3);
        Ps[r] = EXC * (c0 * c0 + c1 * c1 + c2 * c2 + c3 * c3);
    }
    __syncthreads();

    int j = jbase + tid;
    const float* jr = fb + (size_t)j * 64 + col0;
    float cj0, cj1, cj2 = 0.f, cj3 = 0.f;
    if (ND == 4) {
        float4 v = *(const float4*)jr;
        cj0 = v.x; cj1 = v.y; cj2 = v.z; cj3 = v.w;
    } else {
        cj0 = jr[0]; cj1 = jr[1];
    }
    float Qj = EXC * (cj0 * cj0 + cj1 * cj1 + cj2 * cj2 + cj3 * cj3);
    float m0 = -2.f * EXC * cj0, m1 = -2.f * EXC * cj1;
    float m2 = -2.f * EXC * cj2, m3 = -2.f * EXC * cj3;

    int L4u = FULLI ? NN : min(NN, (L + 3) & ~3);
    int hi = max(lo, min(lo + 256, L4u));
    int cnt = hi - lo;                   /* multiple of 4 */
    int mult = FULLI ? 0 : (lo + 256) - hi;

    float S0 = 0.f, S1 = 0.f, S2 = 0.f, S3 = 0.f;
    float U0 = 0.f, U1 = 0.f, U2 = 0.f, U3 = 0.f;
    for (int i = 0; i < cnt; i += 4) {
#pragma unroll
        for (int u = 0; u < 4; u++) {
            float4 c = cs4[i + u];
            float t = Ps[i + u];
            t = fmaf(c.x, m0, t);
            t = fmaf(c.y, m1, t);
            if (ND == 4) {
                t = fmaf(c.z, m2, t);
                t = fmaf(c.w, m3, t);
            }
            float arg = t + Qj;
            float w = ex2(arg);
            if (u == 0)      { S0 += w; U0 = fmaf(arg, w, U0); }
            else if (u == 1) { S1 += w; U1 = fmaf(arg, w, U1); }
            else if (u == 2) { S2 += w; U2 = fmaf(arg, w, U2); }
            else             { S3 += w; U3 = fmaf(arg, w, U3); }
        }
    }
    if (!FULLI && mult > 0) {
        /* row 511 is guaranteed invalid whenever mult > 0 */
        const float* vr = fb + (size_t)(NN - 1) * 64 + col0;
        float v0 = vr[0], v1 = vr[1];
        float v2 = (ND == 4) ? vr[2] : 0.f, v3 = (ND == 4) ? vr[3] : 0.f;
        float t = EXC * (v0 * v0 + v1 * v1 + v2 * v2 + v3 * v3);
        t = fmaf(v0, m0, t); t = fmaf(v1, m1, t);
        if (ND == 4) { t = fmaf(v2, m2, t); t = fmaf(v3, m3, t); }
        float arg = t + Qj;
        float w = ex2(arg);
        float fm = (float)mult;
        S0 = fmaf(fm, w, S0);
        U0 = fmaf(fm * arg, w, U0);
    }
    int o = ib * NROWS + b * NN + j;
    g_S[o] = (S0 + S1) + (S2 + S3);
    g_T[o] = ((U0 + U1) + (U2 + U3)) * IEXC;
}

/* ---------------- GNN layer: multi-subtile pack-free f32x2 GEMM ----------
 * Block owns 128 rows; A loaded into smem ONCE, then 4 subtiles of 32 rows
 * stream through (x + epilogue coeffs reloaded per subtile). Mainloop is
 * the proven R5 flat unroll-8 form (no manual pipelining).
 */
template <int Din>
__global__ void __launch_bounds__(256)
layer_kernel(int bufIn, int bufOut,
             const float* __restrict__ A,
             const float* __restrict__ bvec,
             const float* __restrict__ gamma,
             const float* __restrict__ beta) {
    constexpr int DP = (Din + 3) & ~3;
    __shared__ __align__(16) float As[Din][128];
    __shared__ __align__(16) unsigned long long xd[DP][32];
    __shared__ __align__(16) float4 coef[32];
    const float* featIn = bufIn ? g_feat1 : g_feat0;
    float* featOut = bufOut ? g_feat1 : g_feat0;
    int tid = threadIdx.x;
    int row0 = blockIdx.x * 128;
    int b = row0 >> 9;
    int L = g_len[b];
    int tx = tid & 31, ty = tid >> 5;
    int k0 = tx * 2;

    /* invalid-row constant, needed in several paths */
    float2 tbv = make_float2(tanh_fast(beta[k0]), tanh_fast(beta[k0 + 1]));

    if ((row0 & (NN - 1)) >= L) {    /* whole 128-row block invalid */
        for (int r = ty; r < 128; r += 8)
            *(float2*)&featOut[(size_t)(row0 + r) * 64 + k0] = tbv;
        return;
    }

    /* A into smem once (interleaved: col 2k = A1_k, col 2k+1 = A2_k) */
    for (int idx = tid; idx < Din * 64; idx += 256) {
        int d = idx >> 6, k = idx & 63;
        As[d][2 * k]     = A[d * 64 + k];
        As[d][2 * k + 1] = A[(Din + d) * 64 + k];
    }

    /* k-column constants, hoisted across subtiles */
    float a30 = A[2 * Din * 64 + k0], a31 = A[2 * Din * 64 + k0 + 1];
    float bb0 = bvec[k0], bb1 = bvec[k0 + 1];
    float g0 = gamma[k0] * BNS, g1 = gamma[k0 + 1] * BNS;
    float be0 = beta[k0], be1 = beta[k0 + 1];

#pragma unroll 1
    for (int s = 0; s < 4; s++) {
        int r0 = row0 + 32 * s;
        if ((r0 & (NN - 1)) >= L) {  /* subtile fully invalid */
            for (int r = ty; r < 32; r += 8)
                *(float2*)&featOut[(size_t)(r0 + r) * 64 + k0] = tbv;
            continue;                /* uniform branch: no xd touch, no sync */
        }
        __syncthreads();             /* xd/coef reads of prev subtile done */
        if (tid < 32) {
            int row = r0 + tid;
            float m = g_mask[row];
            float S = g_S[row] + g_S[NROWS + row];
            float T = g_T[row] + g_T[NROWS + row];
            coef[tid] = make_float4(fmaf(m, S, -1.f), m * T, m, 0.f);
        }
        for (int idx = tid; idx < 32 * (DP / 4); idx += 256) {
            int r = idx & 31, dq = idx >> 5;
            float4 v = *(const float4*)&featIn[(size_t)(r0 + r) * 64 + dq * 4];
            xd[dq * 4 + 0][r] = pack2(v.x, v.x);
            xd[dq * 4 + 1][r] = pack2(v.y, v.y);
            xd[dq * 4 + 2][r] = pack2(v.z, v.z);
            xd[dq * 4 + 3][r] = pack2(v.w, v.w);
        }
        __syncthreads();

        unsigned long long acc00 = 0, acc01 = 0, acc10 = 0, acc11 = 0;
        unsigned long long acc20 = 0, acc21 = 0, acc30 = 0, acc31 = 0;
#pragma unroll 8
        for (int d = 0; d < Din; d++) {
            ulonglong2 ap = *(const ulonglong2*)&As[d][tx * 4];
            ulonglong2 xa = *(const ulonglong2*)&xd[d][ty * 4];
            ulonglong2 xb = *(const ulonglong2*)&xd[d][ty * 4 + 2];
            acc00 = ffma2(xa.x, ap.x, acc00);
            acc01 = ffma2(xa.x, ap.y, acc01);
            acc10 = ffma2(xa.y, ap.x, acc10);
            acc11 = ffma2(xa.y, ap.y, acc11);
            acc20 = ffma2(xb.x, ap.x, acc20);
            acc21 = ffma2(xb.x, ap.y, acc21);
            acc30 = ffma2(xb.y, ap.x, acc30);
            acc31 = ffma2(xb.y, ap.y, acc31);
        }

        unsigned long long a0[4] = {acc00, acc10, acc20, acc30};
        unsigned long long a1[4] = {acc01, acc11, acc21, acc31};
#pragma unroll
        for (int r = 0; r < 4; r++) {
            int row = r0 + ty * 4 + r;
            float4 cf = coef[ty * 4 + r];    /* (msm1, mt, m) broadcast */
            float2 uv0 = unpack2(a0[r]);
            float2 uv1 = unpack2(a1[r]);
            float val0 = (fmaf(cf.x, uv0.y, uv0.x) + fmaf(cf.y, a30, bb0)) * cf.z;
            float val1 = (fmaf(cf.x, uv1.y, uv1.x) + fmaf(cf.y, a31, bb1)) * cf.z;
            *(float2*)&featOut[(size_t)row * 64 + k0] =
                make_float2(tanh_fast(fmaf(g0, val0, be0)),
                            tanh_fast(fmaf(g1, val1, be1)));
        }
    }
}

/* ---------------- dense head --------------------------------------------- */
/* split-K partial: x(64,32768)@dW0(32768,128); 256 blocks x K-slab 128. */
__global__ void dense0_partial(const float* __restrict__ dW0) {
    __shared__ float xsT[128][68];   /* [kk][m], padded */
    int tid = threadIdx.x;           /* 128 */
    int k0 = blockIdx.x * 128;
    for (int idx = tid; idx < 128 * 64; idx += 128) {
        int kk = idx & 127, m = idx >> 7;
        xsT[kk][m] = g_feat1[(size_t)m * 32768 + k0 + kk];
    }
    __syncthreads();
    int n = tid;
    unsigned long long acc[32];
#pragma unroll
    for (int mp = 0; mp < 32; mp++) acc[mp] = 0ull;
#pragma unroll 2
    for (int kk = 0; kk < 128; kk++) {
        float w = dW0[(size_t)(k0 + kk) * 128 + n];
        unsigned long long wd = pack2(w, w);
        const float* xr = &xsT[kk][0];
#pragma unroll
        for (int mq = 0; mq < 16; mq++) {
            ulonglong2 xp = *(const ulonglong2*)&xr[mq * 4];
            acc[2 * mq]     = ffma2(xp.x, wd, acc[2 * mq]);
            acc[2 * mq + 1] = ffma2(xp.y, wd, acc[2 * mq + 1]);
        }
    }
    float* p = g_part + (size_t)blockIdx.x * 8192;
#pragma unroll
    for (int mp = 0; mp < 32; mp++) {
        float2 v = unpack2(acc[mp]);
        p[(2 * mp) * 128 + n] = v.x;
        p[(2 * mp + 1) * 128 + n] = v.y;
    }
}

/* deterministic fixed-order reduce + bias + bn + sigmoid (MLP via unroll) */
__global__ void dense0_reduce(const float* __restrict__ db0,
                              const float* __restrict__ dg,
                              const float* __restrict__ dbt) {
    int idx = blockIdx.x * 256 + threadIdx.x;   /* 8192 */
    float s = 0.f;
#pragma unroll 16
    for (int p = 0; p < 256; p++) s += g_part[(size_t)p * 8192 + idx];
    int n = idx & 127;
    float v = s + db0[n];
    v = fmaf(dg[n] * BNS, v, dbt[n]);
    g_h0[idx] = sigmoid_fast(v);
}

/* h0(64,128)@dW1(128,128) -> sigmoid(bn) -> @W2(128,2)+b2 -> out(64,4) */
__global__ void head_kernel(const float* __restrict__ dW1,
                            const float* __restrict__ db1,
                            const float* __restrict__ dg,
                            const float* __restrict__ dbt,
                            const float* __restrict__ W2,
                            const float* __restrict__ b2,
                            float* __restrict__ out) {
    __shared__ float h0[64][128];
    __shared__ float h1[16][128];
    int tid = threadIdx.x;           /* 128 */
    int m0 = blockIdx.x * 16;
    for (int idx = tid; idx < 8192; idx += 128)
        h0[idx >> 7][idx & 127] = g_h0[idx];
    __syncthreads();
    int n = tid;
    float acc[16];
#pragma unroll
    for (int m = 0; m < 16; m++) acc[m] = db1[n];
    for (int k = 0; k < 128; k++) {
        float w = dW1[k * 128 + n];
#pragma unroll
        for (int m = 0; m < 16; m++) acc[m] = fmaf(h0[m0 + m][k], w, acc[m]);
    }
    float g = dg[128 + n] * BNS, bt = dbt[128 + n];
#pragma unroll
    for (int m = 0; m < 16; m++)
        h1[m][n] = sigmoid_fast(fmaf(g, acc[m], bt));
    __syncthreads();
    if (tid < 16) {
        int m = tid;
        float o0 = b2[0], o1 = b2[1];
        for (int nn = 0; nn < 128; nn++) {
            float h = h1[m][nn];
            o0 = fmaf(h, W2[2 * nn], o0);
            o1 = fmaf(h, W2[2 * nn + 1], o1);
        }
        out[(m0 + m) * 4 + 0] = o0;
        out[(m0 + m) * 4 + 1] = o1;
        out[(m0 + m) * 4 + 2] = 0.f;
        out[(m0 + m) * 4 + 3] = 0.f;
    }
}

/* ---------------- launch -------------------------------------------------- */
extern "C" void kernel_launch(void* const* d_in, const int* in_sizes, int n_in,
                              void* d_out, int out_size) {
    const float* xx        = (const float*)d_in[0];
    const float* emb1      = (const float*)d_in[1];
    const float* emb2      = (const float*)d_in[2];
    const float* emb3      = (const float*)d_in[3];
    const float* A0        = (const float*)d_in[4];
    const float* b0        = (const float*)d_in[5];
    const float* A_rest    = (const float*)d_in[6];
    const float* b_rest    = (const float*)d_in[7];
    const float* bn_gamma  = (const float*)d_in[8];
    const float* bn_beta   = (const float*)d_in[9];
    const float* dW0       = (const float*)d_in[10];
    const float* db0       = (const float*)d_in[11];
    const float* dW1       = (const float*)d_in[12];
    const float* db1       = (const float*)d_in[13];
    const float* dbn_gamma = (const float*)d_in[14];
    const float* dbn_beta  = (const float*)d_in[15];
    const float* W2        = (const float*)d_in[16];
    const float* b2        = (const float*)d_in[17];
    float* out = (float*)d_out;

    prep_kernel<<<NROWS / 256, 256>>>(xx, emb1, emb2, emb3);
    len_kernel<<<BB, 256>>>();

    /* layer 0: Din=33, c = cols 31..32, full i-range (c from raw xx) */
    pair_kernel<2, 1><<<dim3(4, 2, BB), 128>>>(0, 31);
    layer_kernel<33><<<NROWS / 128, 256>>>(0, 1, A0, b0, bn_gamma, bn_beta);

    /* layers 1..4: Din=64, c = cols 60..63; ping-pong */
    for (int l = 1; l < 5; l++) {
        int in = l & 1;
        int outb = in ^ 1;
        pair_kernel<4, 0><<<dim3(4, 2, BB), 128>>>(in, 60);
        layer_kernel<64><<<NROWS / 128, 256>>>(in, outb,
                                          A_rest + (size_t)(l - 1) * 129 * 64,
                                          b_rest + (size_t)(l - 1) * 64,
                                          bn_gamma + (size_t)l * 64,
                                          bn_beta + (size_t)l * 64);
    }

    dense0_partial<<<256, 128>>>(dW0);
    dense0_reduce<<<32, 256>>>(db0, dbn_gamma, dbn_beta);
    head_kernel<<<4, 128>>>(dW1, db1, dbn_gamma, dbn_beta, W2, b2, out);
}

// round 11
// speedup vs baseline: 1.5206x; 1.1405x over previous
#include <cuda_runtime.h>
#include <cstdint>

#define BB 64
#define NN 512
#define NROWS (BB*NN)            /* 32768 */
#define BNS  0.9995003746f       /* 1/sqrt(1+1e-3) */
#define EXC  (-14.4269504089f)   /* -10*log2(e) */
#define IEXC (-0.0693147180560f) /* 1/EXC */
#define L2E  1.4426950409f

/* ---------------- scratch: __device__ globals ---------------------------- */
__device__ float g_feat0[NROWS * 64];
__device__ float g_feat1[NROWS * 64];
__device__ float g_mask[NROWS];
__device__ float g_S[2 * NROWS];
__device__ float g_T[2 * NROWS];
__device__ int   g_len[BB];
__device__ float g_part[512 * 64 * 128];
__device__ float g_h0[64 * 128];

/* ---------------- helpers ------------------------------------------------- */
__device__ __forceinline__ float ex2(float x) {
    float r; asm("ex2.approx.ftz.f32 %0, %1;" : "=f"(r) : "f"(x)); return r;
}
__device__ __forceinline__ float rcpf(float x) {
    float r; asm("rcp.approx.ftz.f32 %0, %1;" : "=f"(r) : "f"(x)); return r;
}
__device__ __forceinline__ float tanh_fast(float x) {
    float e = ex2(x * (2.f * L2E));
    return fmaf(-2.f, rcpf(e + 1.f), 1.f);
}
__device__ __forceinline__ float sigmoid_fast(float x) {
    return rcpf(1.f + ex2(-L2E * x));
}
__device__ __forceinline__ unsigned long long ffma2(unsigned long long a,
                                                    unsigned long long b,
                                                    unsigned long long c) {
    unsigned long long d;
    asm("fma.rn.f32x2 %0, %1, %2, %3;" : "=l"(d) : "l"(a), "l"(b), "l"(c));
    return d;
}
__device__ __forceinline__ unsigned long long pack2(float x, float y) {
    unsigned long long d;
    asm("mov.b64 %0, {%1, %2};" : "=l"(d) : "f"(x), "f"(y));
    return d;
}
__device__ __forceinline__ float2 unpack2(unsigned long long v) {
    float2 r;
    asm("mov.b64 {%0, %1}, %2;" : "=f"(r.x), "=f"(r.y) : "l"(v));
    return r;
}

/* ---------------- prep: coalesced feature build --------------------------
 * Block = 256 threads / 64 rows. Stage xx rows in smem (coalesced LDG),
 * then write g_feat0 with (row,col) mapping -> fully coalesced STG.
 */
__global__ void prep_kernel(const float* __restrict__ xx,
                            const float* __restrict__ e1,
                            const float* __restrict__ e2,
                            const float* __restrict__ e3) {
    __shared__ float xs[64 * 30];
    int row0 = blockIdx.x * 64;
    int tid = threadIdx.x;
    const float* src = xx + (size_t)row0 * 30;
    for (int i = tid; i < 64 * 30; i += 256) xs[i] = src[i];
    __syncthreads();
    if (tid < 64) g_mask[row0 + tid] = xs[tid * 30];
    for (int idx = tid; idx < 64 * 64; idx += 256) {
        int r = idx >> 6, c = idx & 63;
        const float* xr = &xs[r * 30];
        float v;
        if (c < 6) {
            int sel = c >> 1;
            int ei = (int)fabsf(xr[27 + sel]);
            const float* e = (sel == 0) ? e1 : ((sel == 1) ? e2 : e3);
            v = e[2 * ei + (c & 1)];
        } else if (c < 33) {
            v = xr[c - 6];
        } else {
            v = 0.f;
        }
        g_feat0[(size_t)(row0 + r) * 64 + c] = v;
    }
}

/* ---------------- per-batch valid length (mask is a 1/0 prefix) ---------- */
__global__ void len_kernel() {
    __shared__ float red[256];
    int b = blockIdx.x, tid = threadIdx.x;
    red[tid] = g_mask[b * NN + tid] + g_mask[b * NN + 256 + tid];
    __syncthreads();
    for (int o = 128; o > 0; o >>= 1) {
        if (tid < o) red[tid] += red[tid + o];
        __syncthreads();
    }
    if (tid == 0) g_len[b] = (int)(red[0] + 0.5f);
}

/* ---------------- pairwise S/T kernel (dot-product form) ------------------ */
template <int ND, int FULLI>
__global__ void pair_kernel(int bufIn, int col0) {
    __shared__ float4 cs4[256];
    __shared__ float  Ps[256];
    const float* feat = bufIn ? g_feat1 : g_feat0;
    int b = blockIdx.z;
    int L = g_len[b];
    int jbase = blockIdx.x * 128;
    if (jbase >= L) return;
    int ib = blockIdx.y;
    int lo = ib * 256;
    int tid = threadIdx.x;
    const float* fb = feat + (size_t)b * NN * 64;

    for (int r = tid; r < 256; r += 128) {
        const float* rowp = fb + (size_t)(lo + r) * 64 + col0;
        float c0, c1, c2 = 0.f, c3 = 0.f;
        if (ND == 4) {
            float4 v = *(const float4*)rowp;
            c0 = v.x; c1 = v.y; c2 = v.z; c3 = v.w;
        } else {
            c0 = rowp[0]; c1 = rowp[1];
        }
        cs4[r] = make_float4(c0, c1, c2, c3);
        Ps[r] = EXC * (c0 * c0 + c1 * c1 + c2 * c2 + c3 * c3);
    }
    __syncthreads();

    int j = jbase + tid;
    const float* jr = fb + (size_t)j * 64 + col0;
    float cj0, cj1, cj2 = 0.f, cj3 = 0.f;
    if (ND == 4) {
        float4 v = *(const float4*)jr;
        cj0 = v.x; cj1 = v.y; cj2 = v.z; cj3 = v.w;
    } else {
        cj0 = jr[0]; cj1 = jr[1];
    }
    float Qj = EXC * (cj0 * cj0 + cj1 * cj1 + cj2 * cj2 + cj3 * cj3);
    float m0 = -2.f * EXC * cj0, m1 = -2.f * EXC * cj1;
    float m2 = -2.f * EXC * cj2, m3 = -2.f * EXC * cj3;

    int L4u = FULLI ? NN : min(NN, (L + 3) & ~3);
    int hi = max(lo, min(lo + 256, L4u));
    int cnt = hi - lo;                   /* multiple of 4 */
    int mult = FULLI ? 0 : (lo + 256) - hi;

    float S0 = 0.f, S1 = 0.f, S2 = 0.f, S3 = 0.f;
    float U0 = 0.f, U1 = 0.f, U2 = 0.f, U3 = 0.f;
    for (int i = 0; i < cnt; i += 4) {
#pragma unroll
        for (int u = 0; u < 4; u++) {
            float4 c = cs4[i + u];
            float t = Ps[i + u];
            t = fmaf(c.x, m0, t);
            t = fmaf(c.y, m1, t);
            if (ND == 4) {
                t = fmaf(c.z, m2, t);
                t = fmaf(c.w, m3, t);
            }
            float arg = t + Qj;
            float w = ex2(arg);
            if (u == 0)      { S0 += w; U0 = fmaf(arg, w, U0); }
            else if (u == 1) { S1 += w; U1 = fmaf(arg, w, U1); }
            else if (u == 2) { S2 += w; U2 = fmaf(arg, w, U2); }
            else             { S3 += w; U3 = fmaf(arg, w, U3); }
        }
    }
    if (!FULLI && mult > 0) {
        /* row 511 is guaranteed invalid whenever mult > 0 */
        const float* vr = fb + (size_t)(NN - 1) * 64 + col0;
        float v0 = vr[0], v1 = vr[1];
        float v2 = (ND == 4) ? vr[2] : 0.f, v3 = (ND == 4) ? vr[3] : 0.f;
        float t = EXC * (v0 * v0 + v1 * v1 + v2 * v2 + v3 * v3);
        t = fmaf(v0, m0, t); t = fmaf(v1, m1, t);
        if (ND == 4) { t = fmaf(v2, m2, t); t = fmaf(v3, m3, t); }
        float arg = t + Qj;
        float w = ex2(arg);
        float fm = (float)mult;
        S0 = fmaf(fm, w, S0);
        U0 = fmaf(fm * arg, w, U0);
    }
    int o = ib * NROWS + b * NN + j;
    g_S[o] = (S0 + S1) + (S2 + S3);
    g_T[o] = ((U0 + U1) + (U2 + U3)) * IEXC;
}

/* ---------------- GNN layer: R5 shape + early epilogue-coef loads --------
 * Grid 1024 x 32 rows, flat unroll-8 mainloop (proven fastest). The only
 * change vs R5: per-row epilogue coefficients (msm1, mt, m) are loaded
 * BEFORE __syncthreads, so barrier + mainloop hide their latency and the
 * epilogue tail has no global loads.
 */
template <int Din>
__global__ void __launch_bounds__(256)
layer_kernel(int bufIn, int bufOut,
             const float* __restrict__ A,
             const float* __restrict__ bvec,
             const float* __restrict__ gamma,
             const float* __restrict__ beta) {
    constexpr int DP = (Din + 3) & ~3;
    __shared__ __align__(16) float As[Din][128];
    __shared__ __align__(16) unsigned long long xd[DP][32];
    const float* featIn = bufIn ? g_feat1 : g_feat0;
    float* featOut = bufOut ? g_feat1 : g_feat0;
    int tid = threadIdx.x;
    int row0 = blockIdx.x * 32;
    int b = row0 >> 9;
    int L = g_len[b];
    int tx = tid & 31, ty = tid >> 5;
    int k0 = tx * 2;

    if ((row0 & (NN - 1)) >= L) {    /* all 32 rows invalid: out = tanh(beta) */
        float2 v = make_float2(tanh_fast(beta[k0]), tanh_fast(beta[k0 + 1]));
        for (int r = ty; r < 32; r += 8)
            *(float2*)&featOut[(size_t)(row0 + r) * 64 + k0] = v;
        return;
    }

    /* early per-row epilogue coefficients: latency hidden by barrier+loop */
    float cmsm1[4], cmt[4], cm[4];
#pragma unroll
    for (int r = 0; r < 4; r++) {
        int row = row0 + ty * 4 + r;
        float m = g_mask[row];
        float S = g_S[row] + g_S[NROWS + row];
        float T = g_T[row] + g_T[NROWS + row];
        cmsm1[r] = fmaf(m, S, -1.f);
        cmt[r] = m * T;
        cm[r] = m;
    }

    for (int idx = tid; idx < Din * 64; idx += 256) {
        int d = idx >> 6, k = idx & 63;
        As[d][2 * k]     = A[d * 64 + k];
        As[d][2 * k + 1] = A[(Din + d) * 64 + k];
    }
    for (int idx = tid; idx < 32 * (DP / 4); idx += 256) {
        int r = idx & 31, dq = idx >> 5;
        float4 v = *(const float4*)&featIn[(size_t)(row0 + r) * 64 + dq * 4];
        xd[dq * 4 + 0][r] = pack2(v.x, v.x);
        xd[dq * 4 + 1][r] = pack2(v.y, v.y);
        xd[dq * 4 + 2][r] = pack2(v.z, v.z);
        xd[dq * 4 + 3][r] = pack2(v.w, v.w);
    }
    __syncthreads();

    unsigned long long acc00 = 0, acc01 = 0, acc10 = 0, acc11 = 0;
    unsigned long long acc20 = 0, acc21 = 0, acc30 = 0, acc31 = 0;
#pragma unroll 8
    for (int d = 0; d < Din; d++) {
        ulonglong2 ap = *(const ulonglong2*)&As[d][tx * 4];
        ulonglong2 xa = *(const ulonglong2*)&xd[d][ty * 4];
        ulonglong2 xb = *(const ulonglong2*)&xd[d][ty * 4 + 2];
        acc00 = ffma2(xa.x, ap.x, acc00);
        acc01 = ffma2(xa.x, ap.y, acc01);
        acc10 = ffma2(xa.y, ap.x, acc10);
        acc11 = ffma2(xa.y, ap.y, acc11);
        acc20 = ffma2(xb.x, ap.x, acc20);
        acc21 = ffma2(xb.x, ap.y, acc21);
        acc30 = ffma2(xb.y, ap.x, acc30);
        acc31 = ffma2(xb.y, ap.y, acc31);
    }

    float a30 = A[2 * Din * 64 + k0], a31 = A[2 * Din * 64 + k0 + 1];
    float bb0 = bvec[k0], bb1 = bvec[k0 + 1];
    float g0 = gamma[k0] * BNS, g1 = gamma[k0 + 1] * BNS;
    float be0 = beta[k0], be1 = beta[k0 + 1];

    unsigned long long a0[4] = {acc00, acc10, acc20, acc30};
    unsigned long long a1[4] = {acc01, acc11, acc21, acc31};
#pragma unroll
    for (int r = 0; r < 4; r++) {
        int row = row0 + ty * 4 + r;
        float2 uv0 = unpack2(a0[r]);
        float2 uv1 = unpack2(a1[r]);
        float val0 = (fmaf(cmsm1[r], uv0.y, uv0.x) + fmaf(cmt[r], a30, bb0)) * cm[r];
        float val1 = (fmaf(cmsm1[r], uv1.y, uv1.x) + fmaf(cmt[r], a31, bb1)) * cm[r];
        *(float2*)&featOut[(size_t)row * 64 + k0] =
            make_float2(tanh_fast(fmaf(g0, val0, be0)),
                        tanh_fast(fmaf(g1, val1, be1)));
    }
}

/* ---------------- dense head --------------------------------------------- */
/* split-K partial: x(64,32768)@dW0(32768,128); 512 blocks x K-slab 64. */
__global__ void dense0_partial(const float* __restrict__ dW0) {
    __shared__ float xsT[64][68];    /* [kk][m], padded */
    int tid = threadIdx.x;           /* 128 */
    int k0 = blockIdx.x * 64;
    for (int idx = tid; idx < 64 * 64; idx += 128) {
        int kk = idx & 63, m = idx >> 6;
        xsT[kk][m] = g_feat1[(size_t)m * 32768 + k0 + kk];
    }
    __syncthreads();
    int n = tid;
    unsigned long long acc[32];
#pragma unroll
    for (int mp = 0; mp < 32; mp++) acc[mp] = 0ull;
#pragma unroll 2
    for (int kk = 0; kk < 64; kk++) {
        float w = dW0[(size_t)(k0 + kk) * 128 + n];
        unsigned long long wd = pack2(w, w);
        const float* xr = &xsT[kk][0];
#pragma unroll
        for (int mq = 0; mq < 16; mq++) {
            ulonglong2 xp = *(const ulonglong2*)&xr[mq * 4];
            acc[2 * mq]     = ffma2(xp.x, wd, acc[2 * mq]);
            acc[2 * mq + 1] = ffma2(xp.y, wd, acc[2 * mq + 1]);
        }
    }
    float* p = g_part + (size_t)blockIdx.x * 8192;
#pragma unroll
    for (int mp = 0; mp < 32; mp++) {
        float2 v = unpack2(acc[mp]);
        p[(2 * mp) * 128 + n] = v.x;
        p[(2 * mp + 1) * 128 + n] = v.y;
    }
}

/* deterministic fixed-order reduce + bias + bn + sigmoid (MLP via unroll) */
__global__ void dense0_reduce(const float* __restrict__ db0,
                              const float* __restrict__ dg,
                              const float* __restrict__ dbt) {
    int idx = blockIdx.x * 256 + threadIdx.x;   /* 8192 */
    float s = 0.f;
#pragma unroll 16
    for (int p = 0; p < 512; p++) s += g_part[(size_t)p * 8192 + idx];
    int n = idx & 127;
    float v = s + db0[n];
    v = fmaf(dg[n] * BNS, v, dbt[n]);
    g_h0[idx] = sigmoid_fast(v);
}

/* h0(64,128)@dW1(128,128) -> sigmoid(bn) -> @W2(128,2)+b2 -> out(64,4) */
__global__ void head_kernel(const float* __restrict__ dW1,
                            const float* __restrict__ db1,
                            const float* __restrict__ dg,
                            const float* __restrict__ dbt,
                            const float* __restrict__ W2,
                            const float* __restrict__ b2,
                            float* __restrict__ out) {
    __shared__ float h0[64][128];
    __shared__ float h1[16][128];
    int tid = threadIdx.x;           /* 128 */
    int m0 = blockIdx.x * 16;
    for (int idx = tid; idx < 8192; idx += 128)
        h0[idx >> 7][idx & 127] = g_h0[idx];
    __syncthreads();
    int n = tid;
    float acc[16];
#pragma unroll
    for (int m = 0; m < 16; m++) acc[m] = db1[n];
    for (int k = 0; k < 128; k++) {
        float w = dW1[k * 128 + n];
#pragma unroll
        for (int m = 0; m < 16; m++) acc[m] = fmaf(h0[m0 + m][k], w, acc[m]);
    }
    float g = dg[128 + n] * BNS, bt = dbt[128 + n];
#pragma unroll
    for (int m = 0; m < 16; m++)
        h1[m][n] = sigmoid_fast(fmaf(g, acc[m], bt));
    __syncthreads();
    if (tid < 16) {
        int m = tid;
        float o0 = b2[0], o1 = b2[1];
        for (int nn = 0; nn < 128; nn++) {
            float h = h1[m][nn];
            o0 = fmaf(h, W2[2 * nn], o0);
            o1 = fmaf(h, W2[2 * nn + 1], o1);
        }
        out[(m0 + m) * 4 + 0] = o0;
        out[(m0 + m) * 4 + 1] = o1;
        out[(m0 + m) * 4 + 2] = 0.f;
        out[(m0 + m) * 4 + 3] = 0.f;
    }
}

/* ---------------- launch -------------------------------------------------- */
extern "C" void kernel_launch(void* const* d_in, const int* in_sizes, int n_in,
                              void* d_out, int out_size) {
    const float* xx        = (const float*)d_in[0];
    const float* emb1      = (const float*)d_in[1];
    const float* emb2      = (const float*)d_in[2];
    const float* emb3      = (const float*)d_in[3];
    const float* A0        = (const float*)d_in[4];
    const float* b0        = (const float*)d_in[5];
    const float* A_rest    = (const float*)d_in[6];
    const float* b_rest    = (const float*)d_in[7];
    const float* bn_gamma  = (const float*)d_in[8];
    const float* bn_beta   = (const float*)d_in[9];
    const float* dW0       = (const float*)d_in[10];
    const float* db0       = (const float*)d_in[11];
    const float* dW1       = (const float*)d_in[12];
    const float* db1       = (const float*)d_in[13];
    const float* dbn_gamma = (const float*)d_in[14];
    const float* dbn_beta  = (const float*)d_in[15];
    const float* W2        = (const float*)d_in[16];
    const float* b2        = (const float*)d_in[17];
    float* out = (float*)d_out;

    prep_kernel<<<NROWS / 64, 256>>>(xx, emb1, emb2, emb3);
    len_kernel<<<BB, 256>>>();

    /* layer 0: Din=33, c = cols 31..32, full i-range (c from raw xx) */
    pair_kernel<2, 1><<<dim3(4, 2, BB), 128>>>(0, 31);
    layer_kernel<33><<<NROWS / 32, 256>>>(0, 1, A0, b0, bn_gamma, bn_beta);

    /* layers 1..4: Din=64, c = cols 60..63; ping-pong */
    for (int l = 1; l < 5; l++) {
        int in = l & 1;
        int outb = in ^ 1;
        pair_kernel<4, 0><<<dim3(4, 2, BB), 128>>>(in, 60);
        layer_kernel<64><<<NROWS / 32, 256>>>(in, outb,
                                          A_rest + (size_t)(l - 1) * 129 * 64,
                                          b_rest + (size_t)(l - 1) * 64,
                                          bn_gamma + (size_t)l * 64,
                                          bn_beta + (size_t)l * 64);
    }

    dense0_partial<<<512, 128>>>(dW0);
    dense0_reduce<<<32, 256>>>(db0, dbn_gamma, dbn_beta);
    head_kernel<<<4, 128>>>(dW1, db1, dbn_gamma, dbn_beta, W2, b2, out);
}

// round 12
// speedup vs baseline: 1.6648x; 1.0949x over previous
#include <cuda_runtime.h>
#include <cstdint>

#define BB 64
#define NN 512
#define NROWS (BB*NN)            /* 32768 */
#define BNS  0.9995003746f       /* 1/sqrt(1+1e-3) */
#define EXC  (-14.4269504089f)   /* -10*log2(e) */
#define IEXC (-0.0693147180560f) /* 1/EXC */
#define L2E  1.4426950409f

/* ---------------- scratch: __device__ globals ---------------------------- */
__device__ float g_feat0[NROWS * 64];
__device__ float g_feat1[NROWS * 64];
__device__ float g_mask[NROWS];
__device__ float g_S[2 * NROWS];
__device__ float g_T[2 * NROWS];
__device__ int   g_len[BB];
__device__ float g_part[512 * 64 * 128];
__device__ float g_h0[64 * 128];

/* ---------------- helpers ------------------------------------------------- */
__device__ __forceinline__ float ex2(float x) {
    float r; asm("ex2.approx.ftz.f32 %0, %1;" : "=f"(r) : "f"(x)); return r;
}
__device__ __forceinline__ float rcpf(float x) {
    float r; asm("rcp.approx.ftz.f32 %0, %1;" : "=f"(r) : "f"(x)); return r;
}
__device__ __forceinline__ float tanh_fast(float x) {
    float e = ex2(x * (2.f * L2E));
    return fmaf(-2.f, rcpf(e + 1.f), 1.f);
}
__device__ __forceinline__ float sigmoid_fast(float x) {
    return rcpf(1.f + ex2(-L2E * x));
}
__device__ __forceinline__ unsigned long long ffma2(unsigned long long a,
                                                    unsigned long long b,
                                                    unsigned long long c) {
    unsigned long long d;
    asm("fma.rn.f32x2 %0, %1, %2, %3;" : "=l"(d) : "l"(a), "l"(b), "l"(c));
    return d;
}
__device__ __forceinline__ unsigned long long pack2(float x, float y) {
    unsigned long long d;
    asm("mov.b64 %0, {%1, %2};" : "=l"(d) : "f"(x), "f"(y));
    return d;
}
__device__ __forceinline__ float2 unpack2(unsigned long long v) {
    float2 r;
    asm("mov.b64 {%0, %1}, %2;" : "=f"(r.x), "=f"(r.y) : "l"(v));
    return r;
}

/* ---------------- prep: coalesced feature build -------------------------- */
__global__ void prep_kernel(const float* __restrict__ xx,
                            const float* __restrict__ e1,
                            const float* __restrict__ e2,
                            const float* __restrict__ e3) {
    __shared__ float xs[64 * 30];
    int row0 = blockIdx.x * 64;
    int tid = threadIdx.x;
    const float* src = xx + (size_t)row0 * 30;
    for (int i = tid; i < 64 * 30; i += 256) xs[i] = src[i];
    __syncthreads();
    if (tid < 64) g_mask[row0 + tid] = xs[tid * 30];
    for (int idx = tid; idx < 64 * 64; idx += 256) {
        int r = idx >> 6, c = idx & 63;
        const float* xr = &xs[r * 30];
        float v;
        if (c < 6) {
            int sel = c >> 1;
            int ei = (int)fabsf(xr[27 + sel]);
            const float* e = (sel == 0) ? e1 : ((sel == 1) ? e2 : e3);
            v = e[2 * ei + (c & 1)];
        } else if (c < 33) {
            v = xr[c - 6];
        } else {
            v = 0.f;
        }
        g_feat0[(size_t)(row0 + r) * 64 + c] = v;
    }
}

/* ---------------- per-batch valid length (mask is a 1/0 prefix) ---------- */
__global__ void len_kernel() {
    __shared__ float red[256];
    int b = blockIdx.x, tid = threadIdx.x;
    red[tid] = g_mask[b * NN + tid] + g_mask[b * NN + 256 + tid];
    __syncthreads();
    for (int o = 128; o > 0; o >>= 1) {
        if (tid < o) red[tid] += red[tid + o];
        __syncthreads();
    }
    if (tid == 0) g_len[b] = (int)(red[0] + 0.5f);
}

/* ---------------- pairwise S/T kernel (dot-product form) ------------------ */
template <int ND, int FULLI>
__global__ void pair_kernel(int bufIn, int col0) {
    __shared__ float4 cs4[256];
    __shared__ float  Ps[256];
    const float* feat = bufIn ? g_feat1 : g_feat0;
    int b = blockIdx.z;
    int L = g_len[b];
    int jbase = blockIdx.x * 128;
    if (jbase >= L) return;
    int ib = blockIdx.y;
    int lo = ib * 256;
    int tid = threadIdx.x;
    const float* fb = feat + (size_t)b * NN * 64;

    for (int r = tid; r < 256; r += 128) {
        const float* rowp = fb + (size_t)(lo + r) * 64 + col0;
        float c0, c1, c2 = 0.f, c3 = 0.f;
        if (ND == 4) {
            float4 v = *(const float4*)rowp;
            c0 = v.x; c1 = v.y; c2 = v.z; c3 = v.w;
        } else {
            c0 = rowp[0]; c1 = rowp[1];
        }
        cs4[r] = make_float4(c0, c1, c2, c3);
        Ps[r] = EXC * (c0 * c0 + c1 * c1 + c2 * c2 + c3 * c3);
    }
    __syncthreads();

    int j = jbase + tid;
    const float* jr = fb + (size_t)j * 64 + col0;
    float cj0, cj1, cj2 = 0.f, cj3 = 0.f;
    if (ND == 4) {
        float4 v = *(const float4*)jr;
        cj0 = v.x; cj1 = v.y; cj2 = v.z; cj3 = v.w;
    } else {
        cj0 = jr[0]; cj1 = jr[1];
    }
    float Qj = EXC * (cj0 * cj0 + cj1 * cj1 + cj2 * cj2 + cj3 * cj3);
    float m0 = -2.f * EXC * cj0, m1 = -2.f * EXC * cj1;
    float m2 = -2.f * EXC * cj2, m3 = -2.f * EXC * cj3;

    int L4u = FULLI ? NN : min(NN, (L + 3) & ~3);
    int hi = max(lo, min(lo + 256, L4u));
    int cnt = hi - lo;                   /* multiple of 4 */
    int mult = FULLI ? 0 : (lo + 256) - hi;

    float S0 = 0.f, S1 = 0.f, S2 = 0.f, S3 = 0.f;
    float U0 = 0.f, U1 = 0.f, U2 = 0.f, U3 = 0.f;
    for (int i = 0; i < cnt; i += 4) {
#pragma unroll
        for (int u = 0; u < 4; u++) {
            float4 c = cs4[i + u];
            float t = Ps[i + u];
            t = fmaf(c.x, m0, t);
            t = fmaf(c.y, m1, t);
            if (ND == 4) {
                t = fmaf(c.z, m2, t);
                t = fmaf(c.w, m3, t);
            }
            float arg = t + Qj;
            float w = ex2(arg);
            if (u == 0)      { S0 += w; U0 = fmaf(arg, w, U0); }
            else if (u == 1) { S1 += w; U1 = fmaf(arg, w, U1); }
            else if (u == 2) { S2 += w; U2 = fmaf(arg, w, U2); }
            else             { S3 += w; U3 = fmaf(arg, w, U3); }
        }
    }
    if (!FULLI && mult > 0) {
        /* row 511 is guaranteed invalid whenever mult > 0 */
        const float* vr = fb + (size_t)(NN - 1) * 64 + col0;
        float v0 = vr[0], v1 = vr[1];
        float v2 = (ND == 4) ? vr[2] : 0.f, v3 = (ND == 4) ? vr[3] : 0.f;
        float t = EXC * (v0 * v0 + v1 * v1 + v2 * v2 + v3 * v3);
        t = fmaf(v0, m0, t); t = fmaf(v1, m1, t);
        if (ND == 4) { t = fmaf(v2, m2, t); t = fmaf(v3, m3, t); }
        float arg = t + Qj;
        float w = ex2(arg);
        float fm = (float)mult;
        S0 = fmaf(fm, w, S0);
        U0 = fmaf(fm * arg, w, U0);
    }
    int o = ib * NROWS + b * NN + j;
    g_S[o] = (S0 + S1) + (S2 + S3);
    g_T[o] = ((U0 + U1) + (U2 + U3)) * IEXC;
}

/* ---------------- GNN layer: 8-row x 2-k tile (halved A crossbar) --------
 * 128 threads/block, 32 rows, grid 1024. Thread = 8 rows x 2 k: per d-step
 * one LDS.128 of A serves 16 FFMA2 (vs 8 before), halving the
 * distinct-address smem crossbar traffic that bounds this kernel. x-reads
 * are warp-broadcast (free). Epilogue coefficients loaded early with
 * vectorized float4 LDGs; tail has no global loads.
 */
template <int Din>
__global__ void __launch_bounds__(128)
layer_kernel(int bufIn, int bufOut,
             const float* __restrict__ A,
             const float* __restrict__ bvec,
             const float* __restrict__ gamma,
             const float* __restrict__ beta) {
    constexpr int DP = (Din + 3) & ~3;
    __shared__ __align__(16) float As[Din][128];
    __shared__ __align__(16) unsigned long long xd[DP][32];
    const float* featIn = bufIn ? g_feat1 : g_feat0;
    float* featOut = bufOut ? g_feat1 : g_feat0;
    int tid = threadIdx.x;           /* 128 */
    int row0 = blockIdx.x * 32;
    int b = row0 >> 9;
    int L = g_len[b];
    int tx = tid & 31, ty = tid >> 5;    /* ty: 4 row-octets */
    int k0 = tx * 2;
    int r0 = ty * 8;
    int rowb = row0 + r0;                /* 8-aligned row base */

    if ((row0 & (NN - 1)) >= L) {    /* all 32 rows invalid: out = tanh(beta) */
        float2 v = make_float2(tanh_fast(beta[k0]), tanh_fast(beta[k0 + 1]));
#pragma unroll
        for (int r = 0; r < 8; r++)
            *(float2*)&featOut[(size_t)(rowb + r) * 64 + k0] = v;
        return;
    }

    /* early vectorized epilogue coefficients (8 contiguous rows) */
    float4 mv0 = *(const float4*)&g_mask[rowb];
    float4 mv1 = *(const float4*)&g_mask[rowb + 4];
    float4 sa0 = *(const float4*)&g_S[rowb];
    float4 sa1 = *(const float4*)&g_S[rowb + 4];
    float4 sb0 = *(const float4*)&g_S[NROWS + rowb];
    float4 sb1 = *(const float4*)&g_S[NROWS + rowb + 4];
    float4 ta0 = *(const float4*)&g_T[rowb];
    float4 ta1 = *(const float4*)&g_T[rowb + 4];
    float4 tb0 = *(const float4*)&g_T[NROWS + rowb];
    float4 tb1 = *(const float4*)&g_T[NROWS + rowb + 4];
    float cm[8]   = {mv0.x, mv0.y, mv0.z, mv0.w, mv1.x, mv1.y, mv1.z, mv1.w};
    float cS[8]   = {sa0.x + sb0.x, sa0.y + sb0.y, sa0.z + sb0.z, sa0.w + sb0.w,
                     sa1.x + sb1.x, sa1.y + sb1.y, sa1.z + sb1.z, sa1.w + sb1.w};
    float cT[8]   = {ta0.x + tb0.x, ta0.y + tb0.y, ta0.z + tb0.z, ta0.w + tb0.w,
                     ta1.x + tb1.x, ta1.y + tb1.y, ta1.z + tb1.z, ta1.w + tb1.w};
    float cmsm1[8], cmt[8];
#pragma unroll
    for (int r = 0; r < 8; r++) {
        cmsm1[r] = fmaf(cm[r], cS[r], -1.f);
        cmt[r] = cm[r] * cT[r];
    }

    /* A into smem (interleaved: col 2k = A1_k, col 2k+1 = A2_k) */
    for (int idx = tid; idx < Din * 64; idx += 128) {
        int d = idx >> 6, k = idx & 63;
        As[d][2 * k]     = A[d * 64 + k];
        As[d][2 * k + 1] = A[(Din + d) * 64 + k];
    }
    /* x duplicated (x,x) into smem, [d][row] */
    for (int idx = tid; idx < 32 * (DP / 4); idx += 128) {
        int r = idx & 31, dq = idx >> 5;
        float4 v = *(const float4*)&featIn[(size_t)(row0 + r) * 64 + dq * 4];
        xd[dq * 4 + 0][r] = pack2(v.x, v.x);
        xd[dq * 4 + 1][r] = pack2(v.y, v.y);
        xd[dq * 4 + 2][r] = pack2(v.z, v.z);
        xd[dq * 4 + 3][r] = pack2(v.w, v.w);
    }
    __syncthreads();

    unsigned long long acc[8][2];
#pragma unroll
    for (int r = 0; r < 8; r++) { acc[r][0] = 0ull; acc[r][1] = 0ull; }

#pragma unroll 8
    for (int d = 0; d < Din; d++) {
        ulonglong2 ap = *(const ulonglong2*)&As[d][tx * 4];    /* 2 k-pairs */
        const ulonglong2* xr = (const ulonglong2*)&xd[d][r0];  /* broadcast */
        ulonglong2 x01 = xr[0];
        ulonglong2 x23 = xr[1];
        ulonglong2 x45 = xr[2];
        ulonglong2 x67 = xr[3];
        acc[0][0] = ffma2(x01.x, ap.x, acc[0][0]);
        acc[0][1] = ffma2(x01.x, ap.y, acc[0][1]);
        acc[1][0] = ffma2(x01.y, ap.x, acc[1][0]);
        acc[1][1] = ffma2(x01.y, ap.y, acc[1][1]);
        acc[2][0] = ffma2(x23.x, ap.x, acc[2][0]);
        acc[2][1] = ffma2(x23.x, ap.y, acc[2][1]);
        acc[3][0] = ffma2(x23.y, ap.x, acc[3][0]);
        acc[3][1] = ffma2(x23.y, ap.y, acc[3][1]);
        acc[4][0] = ffma2(x45.x, ap.x, acc[4][0]);
        acc[4][1] = ffma2(x45.x, ap.y, acc[4][1]);
        acc[5][0] = ffma2(x45.y, ap.x, acc[5][0]);
        acc[5][1] = ffma2(x45.y, ap.y, acc[5][1]);
        acc[6][0] = ffma2(x67.x, ap.x, acc[6][0]);
        acc[6][1] = ffma2(x67.x, ap.y, acc[6][1]);
        acc[7][0] = ffma2(x67.y, ap.x, acc[7][0]);
        acc[7][1] = ffma2(x67.y, ap.y, acc[7][1]);
    }

    float a30 = A[2 * Din * 64 + k0], a31 = A[2 * Din * 64 + k0 + 1];
    float bb0 = bvec[k0], bb1 = bvec[k0 + 1];
    float g0 = gamma[k0] * BNS, g1 = gamma[k0 + 1] * BNS;
    float be0 = beta[k0], be1 = beta[k0 + 1];

#pragma unroll
    for (int r = 0; r < 8; r++) {
        int row = rowb + r;
        float2 uv0 = unpack2(acc[r][0]);   /* (u_k0, v_k0) */
        float2 uv1 = unpack2(acc[r][1]);   /* (u_k1, v_k1) */
        float val0 = (fmaf(cmsm1[r], uv0.y, uv0.x) + fmaf(cmt[r], a30, bb0)) * cm[r];
        float val1 = (fmaf(cmsm1[r], uv1.y, uv1.x) + fmaf(cmt[r], a31, bb1)) * cm[r];
        *(float2*)&featOut[(size_t)row * 64 + k0] =
            make_float2(tanh_fast(fmaf(g0, val0, be0)),
                        tanh_fast(fmaf(g1, val1, be1)));
    }
}

/* ---------------- dense head --------------------------------------------- */
/* split-K partial: x(64,32768)@dW0(32768,128); 512 blocks x K-slab 64. */
__global__ void dense0_partial(const float* __restrict__ dW0) {
    __shared__ float xsT[64][68];    /* [kk][m], padded */
    int tid = threadIdx.x;           /* 128 */
    int k0 = blockIdx.x * 64;
    for (int idx = tid; idx < 64 * 64; idx += 128) {
        int kk = idx & 63, m = idx >> 6;
        xsT[kk][m] = g_feat1[(size_t)m * 32768 + k0 + kk];
    }
    __syncthreads();
    int n = tid;
    unsigned long long acc[32];
#pragma unroll
    for (int mp = 0; mp < 32; mp++) acc[mp] = 0ull;
#pragma unroll 2
    for (int kk = 0; kk < 64; kk++) {
        float w = dW0[(size_t)(k0 + kk) * 128 + n];
        unsigned long long wd = pack2(w, w);
        const float* xr = &xsT[kk][0];
#pragma unroll
        for (int mq = 0; mq < 16; mq++) {
            ulonglong2 xp = *(const ulonglong2*)&xr[mq * 4];
            acc[2 * mq]     = ffma2(xp.x, wd, acc[2 * mq]);
            acc[2 * mq + 1] = ffma2(xp.y, wd, acc[2 * mq + 1]);
        }
    }
    float* p = g_part + (size_t)blockIdx.x * 8192;
#pragma unroll
    for (int mp = 0; mp < 32; mp++) {
        float2 v = unpack2(acc[mp]);
        p[(2 * mp) * 128 + n] = v.x;
        p[(2 * mp + 1) * 128 + n] = v.y;
    }
}

/* deterministic fixed-order reduce + bias + bn + sigmoid (MLP via unroll) */
__global__ void dense0_reduce(const float* __restrict__ db0,
                              const float* __restrict__ dg,
                              const float* __restrict__ dbt) {
    int idx = blockIdx.x * 256 + threadIdx.x;   /* 8192 */
    float s = 0.f;
#pragma unroll 16
    for (int p = 0; p < 512; p++) s += g_part[(size_t)p * 8192 + idx];
    int n = idx & 127;
    float v = s + db0[n];
    v = fmaf(dg[n] * BNS, v, dbt[n]);
    g_h0[idx] = sigmoid_fast(v);
}

/* h0(64,128)@dW1(128,128) -> sigmoid(bn) -> @W2(128,2)+b2 -> out(64,4) */
__global__ void head_kernel(const float* __restrict__ dW1,
                            const float* __restrict__ db1,
                            const float* __restrict__ dg,
                            const float* __restrict__ dbt,
                            const float* __restrict__ W2,
                            const float* __restrict__ b2,
                            float* __restrict__ out) {
    __shared__ float h0[64][128];
    __shared__ float h1[16][128];
    int tid = threadIdx.x;           /* 128 */
    int m0 = blockIdx.x * 16;
    for (int idx = tid; idx < 8192; idx += 128)
        h0[idx >> 7][idx & 127] = g_h0[idx];
    __syncthreads();
    int n = tid;
    float acc[16];
#pragma unroll
    for (int m = 0; m < 16; m++) acc[m] = db1[n];
    for (int k = 0; k < 128; k++) {
        float w = dW1[k * 128 + n];
#pragma unroll
        for (int m = 0; m < 16; m++) acc[m] = fmaf(h0[m0 + m][k], w, acc[m]);
    }
    float g = dg[128 + n] * BNS, bt = dbt[128 + n];
#pragma unroll
    for (int m = 0; m < 16; m++)
        h1[m][n] = sigmoid_fast(fmaf(g, acc[m], bt));
    __syncthreads();
    if (tid < 16) {
        int m = tid;
        float o0 = b2[0], o1 = b2[1];
        for (int nn = 0; nn < 128; nn++) {
            float h = h1[m][nn];
            o0 = fmaf(h, W2[2 * nn], o0);
            o1 = fmaf(h, W2[2 * nn + 1], o1);
        }
        out[(m0 + m) * 4 + 0] = o0;
        out[(m0 + m) * 4 + 1] = o1;
        out[(m0 + m) * 4 + 2] = 0.f;
        out[(m0 + m) * 4 + 3] = 0.f;
    }
}

/* ---------------- launch -------------------------------------------------- */
extern "C" void kernel_launch(void* const* d_in, const int* in_sizes, int n_in,
                              void* d_out, int out_size) {
    const float* xx        = (const float*)d_in[0];
    const float* emb1      = (const float*)d_in[1];
    const float* emb2      = (const float*)d_in[2];
    const float* emb3      = (const float*)d_in[3];
    const float* A0        = (const float*)d_in[4];
    const float* b0        = (const float*)d_in[5];
    const float* A_rest    = (const float*)d_in[6];
    const float* b_rest    = (const float*)d_in[7];
    const float* bn_gamma  = (const float*)d_in[8];
    const float* bn_beta   = (const float*)d_in[9];
    const float* dW0       = (const float*)d_in[10];
    const float* db0       = (const float*)d_in[11];
    const float* dW1       = (const float*)d_in[12];
    const float* db1       = (const float*)d_in[13];
    const float* dbn_gamma = (const float*)d_in[14];
    const float* dbn_beta  = (const float*)d_in[15];
    const float* W2        = (const float*)d_in[16];
    const float* b2        = (const float*)d_in[17];
    float* out = (float*)d_out;

    prep_kernel<<<NROWS / 64, 256>>>(xx, emb1, emb2, emb3);
    len_kernel<<<BB, 256>>>();

    /* layer 0: Din=33, c = cols 31..32, full i-range (c from raw xx) */
    pair_kernel<2, 1><<<dim3(4, 2, BB), 128>>>(0, 31);
    layer_kernel<33><<<NROWS / 32, 128>>>(0, 1, A0, b0, bn_gamma, bn_beta);

    /* layers 1..4: Din=64, c = cols 60..63; ping-pong */
    for (int l = 1; l < 5; l++) {
        int in = l & 1;
        int outb = in ^ 1;
        pair_kernel<4, 0><<<dim3(4, 2, BB), 128>>>(in, 60);
        layer_kernel<64><<<NROWS / 32, 128>>>(in, outb,
                                          A_rest + (size_t)(l - 1) * 129 * 64,
                                          b_rest + (size_t)(l - 1) * 64,
                                          bn_gamma + (size_t)l * 64,
                                          bn_beta + (size_t)l * 64);
    }

    dense0_partial<<<512, 128>>>(dW0);
    dense0_reduce<<<32, 256>>>(db0, dbn_gamma, dbn_beta);
    head_kernel<<<4, 128>>>(dW1, db1, dbn_gamma, dbn_beta, W2, b2, out);
}

// round 13
// speedup vs baseline: 1.6839x; 1.0115x over previous
#include <cuda_runtime.h>
#include <cstdint>

#define BB 64
#define NN 512
#define NROWS (BB*NN)            /* 32768 */
#define BNS  0.9995003746f       /* 1/sqrt(1+1e-3) */
#define EXC  (-14.4269504089f)   /* -10*log2(e) */
#define IEXC (-0.0693147180560f) /* 1/EXC */
#define L2E  1.4426950409f

/* ---------------- scratch: __device__ globals ---------------------------- */
__device__ float g_feat0[NROWS * 64];
__device__ float g_feat1[NROWS * 64];
__device__ float g_mask[NROWS];
__device__ float g_S[2 * NROWS];
__device__ float g_T[2 * NROWS];
__device__ int   g_len[BB];
__device__ float g_part[512 * 64 * 128];
__device__ float g_h0[64 * 128];

/* ---------------- helpers ------------------------------------------------- */
__device__ __forceinline__ float ex2(float x) {
    float r; asm("ex2.approx.ftz.f32 %0, %1;" : "=f"(r) : "f"(x)); return r;
}
__device__ __forceinline__ float rcpf(float x) {
    float r; asm("rcp.approx.ftz.f32 %0, %1;" : "=f"(r) : "f"(x)); return r;
}
__device__ __forceinline__ float tanh_fast(float x) {
    float e = ex2(x * (2.f * L2E));
    return fmaf(-2.f, rcpf(e + 1.f), 1.f);
}
__device__ __forceinline__ float sigmoid_fast(float x) {
    return rcpf(1.f + ex2(-L2E * x));
}
__device__ __forceinline__ unsigned long long ffma2(unsigned long long a,
                                                    unsigned long long b,
                                                    unsigned long long c) {
    unsigned long long d;
    asm("fma.rn.f32x2 %0, %1, %2, %3;" : "=l"(d) : "l"(a), "l"(b), "l"(c));
    return d;
}
__device__ __forceinline__ unsigned long long pack2(float x, float y) {
    unsigned long long d;
    asm("mov.b64 %0, {%1, %2};" : "=l"(d) : "f"(x), "f"(y));
    return d;
}
__device__ __forceinline__ float2 unpack2(unsigned long long v) {
    float2 r;
    asm("mov.b64 {%0, %1}, %2;" : "=f"(r.x), "=f"(r.y) : "l"(v));
    return r;
}

/* ---------------- prep: coalesced feature build -------------------------- */
__global__ void prep_kernel(const float* __restrict__ xx,
                            const float* __restrict__ e1,
                            const float* __restrict__ e2,
                            const float* __restrict__ e3) {
    __shared__ float xs[64 * 30];
    int row0 = blockIdx.x * 64;
    int tid = threadIdx.x;
    const float* src = xx + (size_t)row0 * 30;
    for (int i = tid; i < 64 * 30; i += 256) xs[i] = src[i];
    __syncthreads();
    if (tid < 64) g_mask[row0 + tid] = xs[tid * 30];
    for (int idx = tid; idx < 64 * 64; idx += 256) {
        int r = idx >> 6, c = idx & 63;
        const float* xr = &xs[r * 30];
        float v;
        if (c < 6) {
            int sel = c >> 1;
            int ei = (int)fabsf(xr[27 + sel]);
            const float* e = (sel == 0) ? e1 : ((sel == 1) ? e2 : e3);
            v = e[2 * ei + (c & 1)];
        } else if (c < 33) {
            v = xr[c - 6];
        } else {
            v = 0.f;
        }
        g_feat0[(size_t)(row0 + r) * 64 + c] = v;
    }
}

/* ---------------- per-batch valid length (mask is a 1/0 prefix) ---------- */
__global__ void len_kernel() {
    __shared__ float red[256];
    int b = blockIdx.x, tid = threadIdx.x;
    red[tid] = g_mask[b * NN + tid] + g_mask[b * NN + 256 + tid];
    __syncthreads();
    for (int o = 128; o > 0; o >>= 1) {
        if (tid < o) red[tid] += red[tid + o];
        __syncthreads();
    }
    if (tid == 0) g_len[b] = (int)(red[0] + 0.5f);
}

/* ---------------- pairwise S/T kernel (dot-product form, unroll 8) -------
 * i-range rounded to 8 (L8u). Pad rows [L, L8u) always lie inside the
 * written partial block, so they hold the invalid-row constant; the
 * virtual-row multiplicity shrinks by exactly the padded count.
 */
template <int ND, int FULLI>
__global__ void pair_kernel(int bufIn, int col0) {
    __shared__ float4 cs4[256];
    __shared__ float  Ps[256];
    const float* feat = bufIn ? g_feat1 : g_feat0;
    int b = blockIdx.z;
    int L = g_len[b];
    int jbase = blockIdx.x * 128;
    if (jbase >= L) return;
    int ib = blockIdx.y;
    int lo = ib * 256;
    int tid = threadIdx.x;
    const float* fb = feat + (size_t)b * NN * 64;

    for (int r = tid; r < 256; r += 128) {
        const float* rowp = fb + (size_t)(lo + r) * 64 + col0;
        float c0, c1, c2 = 0.f, c3 = 0.f;
        if (ND == 4) {
            float4 v = *(const float4*)rowp;
            c0 = v.x; c1 = v.y; c2 = v.z; c3 = v.w;
        } else {
            c0 = rowp[0]; c1 = rowp[1];
        }
        cs4[r] = make_float4(c0, c1, c2, c3);
        Ps[r] = EXC * (c0 * c0 + c1 * c1 + c2 * c2 + c3 * c3);
    }
    __syncthreads();

    int j = jbase + tid;
    const float* jr = fb + (size_t)j * 64 + col0;
    float cj0, cj1, cj2 = 0.f, cj3 = 0.f;
    if (ND == 4) {
        float4 v = *(const float4*)jr;
        cj0 = v.x; cj1 = v.y; cj2 = v.z; cj3 = v.w;
    } else {
        cj0 = jr[0]; cj1 = jr[1];
    }
    float Qj = EXC * (cj0 * cj0 + cj1 * cj1 + cj2 * cj2 + cj3 * cj3);
    float m0 = -2.f * EXC * cj0, m1 = -2.f * EXC * cj1;
    float m2 = -2.f * EXC * cj2, m3 = -2.f * EXC * cj3;

    int L8u = FULLI ? NN : min(NN, (L + 7) & ~7);
    int hi = max(lo, min(lo + 256, L8u));
    int cnt = hi - lo;                   /* multiple of 8 */
    int mult = FULLI ? 0 : (lo + 256) - hi;

    float S0 = 0.f, S1 = 0.f, S2 = 0.f, S3 = 0.f;
    float U0 = 0.f, U1 = 0.f, U2 = 0.f, U3 = 0.f;
    for (int i = 0; i < cnt; i += 8) {
#pragma unroll
        for (int u = 0; u < 8; u++) {
            float4 c = cs4[i + u];
            float t = Ps[i + u];
            t = fmaf(c.x, m0, t);
            t = fmaf(c.y, m1, t);
            if (ND == 4) {
                t = fmaf(c.z, m2, t);
                t = fmaf(c.w, m3, t);
            }
            float arg = t + Qj;
            float w = ex2(arg);
            int s = u & 3;
            if (s == 0)      { S0 += w; U0 = fmaf(arg, w, U0); }
            else if (s == 1) { S1 += w; U1 = fmaf(arg, w, U1); }
            else if (s == 2) { S2 += w; U2 = fmaf(arg, w, U2); }
            else             { S3 += w; U3 = fmaf(arg, w, U3); }
        }
    }
    if (!FULLI && mult > 0) {
        /* row 511 is guaranteed invalid whenever mult > 0 */
        const float* vr = fb + (size_t)(NN - 1) * 64 + col0;
        float v0 = vr[0], v1 = vr[1];
        float v2 = (ND == 4) ? vr[2] : 0.f, v3 = (ND == 4) ? vr[3] : 0.f;
        float t = EXC * (v0 * v0 + v1 * v1 + v2 * v2 + v3 * v3);
        t = fmaf(v0, m0, t); t = fmaf(v1, m1, t);
        if (ND == 4) { t = fmaf(v2, m2, t); t = fmaf(v3, m3, t); }
        float arg = t + Qj;
        float w = ex2(arg);
        float fm = (float)mult;
        S0 = fmaf(fm, w, S0);
        U0 = fmaf(fm * arg, w, U0);
    }
    int o = ib * NROWS + b * NN + j;
    g_S[o] = (S0 + S1) + (S2 + S3);
    g_T[o] = ((U0 + U1) + (U2 + U3)) * IEXC;
}

/* ---------------- GNN layer: 8-row x 2-k tile (R12 core) -----------------
 * New vs R12: invalid blocks skip stores entirely unless this is the LAST
 * layer (dense0 reads all rows) or the block contains row 511 (pair of the
 * next layer reads it). Pad rows [L, L8u) are always in partial blocks,
 * which run the full path and write all 32 rows.
 */
template <int Din>
__global__ void __launch_bounds__(128)
layer_kernel(int bufIn, int bufOut, int last,
             const float* __restrict__ A,
             const float* __restrict__ bvec,
             const float* __restrict__ gamma,
             const float* __restrict__ beta) {
    constexpr int DP = (Din + 3) & ~3;
    __shared__ __align__(16) float As[Din][128];
    __shared__ __align__(16) unsigned long long xd[DP][32];
    const float* featIn = bufIn ? g_feat1 : g_feat0;
    float* featOut = bufOut ? g_feat1 : g_feat0;
    int tid = threadIdx.x;           /* 128 */
    int row0 = blockIdx.x * 32;
    int b = row0 >> 9;
    int L = g_len[b];
    int tx = tid & 31, ty = tid >> 5;    /* ty: 4 row-octets */
    int k0 = tx * 2;
    int r0 = ty * 8;
    int rowb = row0 + r0;                /* 8-aligned row base */

    if ((row0 & (NN - 1)) >= L) {    /* all 32 rows invalid */
        /* stores only needed for the last layer (dense0 reads all rows)
           or the row-511 block (read by next pair stage) */
        if (!last && (row0 & (NN - 1)) != NN - 32) return;
        float2 v = make_float2(tanh_fast(beta[k0]), tanh_fast(beta[k0 + 1]));
#pragma unroll
        for (int r = 0; r < 8; r++)
            *(float2*)&featOut[(size_t)(rowb + r) * 64 + k0] = v;
        return;
    }

    /* early vectorized epilogue coefficients (8 contiguous rows) */
    float4 mv0 = *(const float4*)&g_mask[rowb];
    float4 mv1 = *(const float4*)&g_mask[rowb + 4];
    float4 sa0 = *(const float4*)&g_S[rowb];
    float4 sa1 = *(const float4*)&g_S[rowb + 4];
    float4 sb0 = *(const float4*)&g_S[NROWS + rowb];
    float4 sb1 = *(const float4*)&g_S[NROWS + rowb + 4];
    float4 ta0 = *(const float4*)&g_T[rowb];
    float4 ta1 = *(const float4*)&g_T[rowb + 4];
    float4 tb0 = *(const float4*)&g_T[NROWS + rowb];
    float4 tb1 = *(const float4*)&g_T[NROWS + rowb + 4];
    float cm[8]   = {mv0.x, mv0.y, mv0.z, mv0.w, mv1.x, mv1.y, mv1.z, mv1.w};
    float cS[8]   = {sa0.x + sb0.x, sa0.y + sb0.y, sa0.z + sb0.z, sa0.w + sb0.w,
                     sa1.x + sb1.x, sa1.y + sb1.y, sa1.z + sb1.z, sa1.w + sb1.w};
    float cT[8]   = {ta0.x + tb0.x, ta0.y + tb0.y, ta0.z + tb0.z, ta0.w + tb0.w,
                     ta1.x + tb1.x, ta1.y + tb1.y, ta1.z + tb1.z, ta1.w + tb1.w};
    float cmsm1[8], cmt[8];
#pragma unroll
    for (int r = 0; r < 8; r++) {
        cmsm1[r] = fmaf(cm[r], cS[r], -1.f);
        cmt[r] = cm[r] * cT[r];
    }

    /* A into smem (interleaved: col 2k = A1_k, col 2k+1 = A2_k) */
    for (int idx = tid; idx < Din * 64; idx += 128) {
        int d = idx >> 6, k = idx & 63;
        As[d][2 * k]     = A[d * 64 + k];
        As[d][2 * k + 1] = A[(Din + d) * 64 + k];
    }
    /* x duplicated (x,x) into smem, [d][row] */
    for (int idx = tid; idx < 32 * (DP / 4); idx += 128) {
        int r = idx & 31, dq = idx >> 5;
        float4 v = *(const float4*)&featIn[(size_t)(row0 + r) * 64 + dq * 4];
        xd[dq * 4 + 0][r] = pack2(v.x, v.x);
        xd[dq * 4 + 1][r] = pack2(v.y, v.y);
        xd[dq * 4 + 2][r] = pack2(v.z, v.z);
        xd[dq * 4 + 3][r] = pack2(v.w, v.w);
    }
    __syncthreads();

    unsigned long long acc[8][2];
#pragma unroll
    for (int r = 0; r < 8; r++) { acc[r][0] = 0ull; acc[r][1] = 0ull; }

#pragma unroll 8
    for (int d = 0; d < Din; d++) {
        ulonglong2 ap = *(const ulonglong2*)&As[d][tx * 4];    /* 2 k-pairs */
        const ulonglong2* xr = (const ulonglong2*)&xd[d][r0];  /* broadcast */
        ulonglong2 x01 = xr[0];
        ulonglong2 x23 = xr[1];
        ulonglong2 x45 = xr[2];
        ulonglong2 x67 = xr[3];
        acc[0][0] = ffma2(x01.x, ap.x, acc[0][0]);
        acc[0][1] = ffma2(x01.x, ap.y, acc[0][1]);
        acc[1][0] = ffma2(x01.y, ap.x, acc[1][0]);
        acc[1][1] = ffma2(x01.y, ap.y, acc[1][1]);
        acc[2][0] = ffma2(x23.x, ap.x, acc[2][0]);
        acc[2][1] = ffma2(x23.x, ap.y, acc[2][1]);
        acc[3][0] = ffma2(x23.y, ap.x, acc[3][0]);
        acc[3][1] = ffma2(x23.y, ap.y, acc[3][1]);
        acc[4][0] = ffma2(x45.x, ap.x, acc[4][0]);
        acc[4][1] = ffma2(x45.x, ap.y, acc[4][1]);
        acc[5][0] = ffma2(x45.y, ap.x, acc[5][0]);
        acc[5][1] = ffma2(x45.y, ap.y, acc[5][1]);
        acc[6][0] = ffma2(x67.x, ap.x, acc[6][0]);
        acc[6][1] = ffma2(x67.x, ap.y, acc[6][1]);
        acc[7][0] = ffma2(x67.y, ap.x, acc[7][0]);
        acc[7][1] = ffma2(x67.y, ap.y, acc[7][1]);
    }

    float a30 = A[2 * Din * 64 + k0], a31 = A[2 * Din * 64 + k0 + 1];
    float bb0 = bvec[k0], bb1 = bvec[k0 + 1];
    float g0 = gamma[k0] * BNS, g1 = gamma[k0 + 1] * BNS;
    float be0 = beta[k0], be1 = beta[k0 + 1];

#pragma unroll
    for (int r = 0; r < 8; r++) {
        int row = rowb + r;
        float2 uv0 = unpack2(acc[r][0]);   /* (u_k0, v_k0) */
        float2 uv1 = unpack2(acc[r][1]);   /* (u_k1, v_k1) */
        float val0 = (fmaf(cmsm1[r], uv0.y, uv0.x) + fmaf(cmt[r], a30, bb0)) * cm[r];
        float val1 = (fmaf(cmsm1[r], uv1.y, uv1.x) + fmaf(cmt[r], a31, bb1)) * cm[r];
        *(float2*)&featOut[(size_t)row * 64 + k0] =
            make_float2(tanh_fast(fmaf(g0, val0, be0)),
                        tanh_fast(fmaf(g1, val1, be1)));
    }
}

/* ---------------- dense head --------------------------------------------- */
/* split-K partial: x(64,32768)@dW0(32768,128); 512 blocks x K-slab 64. */
__global__ void dense0_partial(const float* __restrict__ dW0) {
    __shared__ float xsT[64][68];    /* [kk][m], padded */
    int tid = threadIdx.x;           /* 128 */
    int k0 = blockIdx.x * 64;
    for (int idx = tid; idx < 64 * 64; idx += 128) {
        int kk = idx & 63, m = idx >> 6;
        xsT[kk][m] = g_feat1[(size_t)m * 32768 + k0 + kk];
    }
    __syncthreads();
    int n = tid;
    unsigned long long acc[32];
#pragma unroll
    for (int mp = 0; mp < 32; mp++) acc[mp] = 0ull;
#pragma unroll 2
    for (int kk = 0; kk < 64; kk++) {
        float w = dW0[(size_t)(k0 + kk) * 128 + n];
        unsigned long long wd = pack2(w, w);
        const float* xr = &xsT[kk][0];
#pragma unroll
        for (int mq = 0; mq < 16; mq++) {
            ulonglong2 xp = *(const ulonglong2*)&xr[mq * 4];
            acc[2 * mq]     = ffma2(xp.x, wd, acc[2 * mq]);
            acc[2 * mq + 1] = ffma2(xp.y, wd, acc[2 * mq + 1]);
        }
    }
    float* p = g_part + (size_t)blockIdx.x * 8192;
#pragma unroll
    for (int mp = 0; mp < 32; mp++) {
        float2 v = unpack2(acc[mp]);
        p[(2 * mp) * 128 + n] = v.x;
        p[(2 * mp + 1) * 128 + n] = v.y;
    }
}

/* deterministic fixed-order reduce + bias + bn + sigmoid (MLP via unroll) */
__global__ void dense0_reduce(const float* __restrict__ db0,
                              const float* __restrict__ dg,
                              const float* __restrict__ dbt) {
    int idx = blockIdx.x * 256 + threadIdx.x;   /* 8192 */
    float s = 0.f;
#pragma unroll 16
    for (int p = 0; p < 512; p++) s += g_part[(size_t)p * 8192 + idx];
    int n = idx & 127;
    float v = s + db0[n];
    v = fmaf(dg[n] * BNS, v, dbt[n]);
    g_h0[idx] = sigmoid_fast(v);
}

/* h0(64,128)@dW1(128,128) -> sigmoid(bn) -> @W2(128,2)+b2 -> out(64,4) */
__global__ void head_kernel(const float* __restrict__ dW1,
                            const float* __restrict__ db1,
                            const float* __restrict__ dg,
                            const float* __restrict__ dbt,
                            const float* __restrict__ W2,
                            const float* __restrict__ b2,
                            float* __restrict__ out) {
    __shared__ float h0[64][128];
    __shared__ float h1[16][128];
    int tid = threadIdx.x;           /* 128 */
    int m0 = blockIdx.x * 16;
    for (int idx = tid; idx < 8192; idx += 128)
        h0[idx >> 7][idx & 127] = g_h0[idx];
    __syncthreads();
    int n = tid;
    float acc[16];
#pragma unroll
    for (int m = 0; m < 16; m++) acc[m] = db1[n];
    for (int k = 0; k < 128; k++) {
        float w = dW1[k * 128 + n];
#pragma unroll
        for (int m = 0; m < 16; m++) acc[m] = fmaf(h0[m0 + m][k], w, acc[m]);
    }
    float g = dg[128 + n] * BNS, bt = dbt[128 + n];
#pragma unroll
    for (int m = 0; m < 16; m++)
        h1[m][n] = sigmoid_fast(fmaf(g, acc[m], bt));
    __syncthreads();
    if (tid < 16) {
        int m = tid;
        float o0 = b2[0], o1 = b2[1];
        for (int nn = 0; nn < 128; nn++) {
            float h = h1[m][nn];
            o0 = fmaf(h, W2[2 * nn], o0);
            o1 = fmaf(h, W2[2 * nn + 1], o1);
        }
        out[(m0 + m) * 4 + 0] = o0;
        out[(m0 + m) * 4 + 1] = o1;
        out[(m0 + m) * 4 + 2] = 0.f;
        out[(m0 + m) * 4 + 3] = 0.f;
    }
}

/* ---------------- launch -------------------------------------------------- */
extern "C" void kernel_launch(void* const* d_in, const int* in_sizes, int n_in,
                              void* d_out, int out_size) {
    const float* xx        = (const float*)d_in[0];
    const float* emb1      = (const float*)d_in[1];
    const float* emb2      = (const float*)d_in[2];
    const float* emb3      = (const float*)d_in[3];
    const float* A0        = (const float*)d_in[4];
    const float* b0        = (const float*)d_in[5];
    const float* A_rest    = (const float*)d_in[6];
    const float* b_rest    = (const float*)d_in[7];
    const float* bn_gamma  = (const float*)d_in[8];
    const float* bn_beta   = (const float*)d_in[9];
    const float* dW0       = (const float*)d_in[10];
    const float* db0       = (const float*)d_in[11];
    const float* dW1       = (const float*)d_in[12];
    const float* db1       = (const float*)d_in[13];
    const float* dbn_gamma = (const float*)d_in[14];
    const float* dbn_beta  = (const float*)d_in[15];
    const float* W2        = (const float*)d_in[16];
    const float* b2        = (const float*)d_in[17];
    float* out = (float*)d_out;

    prep_kernel<<<NROWS / 64, 256>>>(xx, emb1, emb2, emb3);
    len_kernel<<<BB, 256>>>();

    /* layer 0: Din=33, c = cols 31..32, full i-range (c from raw xx) */
    pair_kernel<2, 1><<<dim3(4, 2, BB), 128>>>(0, 31);
    layer_kernel<33><<<NROWS / 32, 128>>>(0, 1, 0, A0, b0, bn_gamma, bn_beta);

    /* layers 1..4: Din=64, c = cols 60..63; ping-pong */
    for (int l = 1; l < 5; l++) {
        int in = l & 1;
        int outb = in ^ 1;
        int last = (l == 4);
        pair_kernel<4, 0><<<dim3(4, 2, BB), 128>>>(in, 60);
        layer_kernel<64><<<NROWS / 32, 128>>>(in, outb, last,
                                          A_rest + (size_t)(l - 1) * 129 * 64,
                                          b_rest + (size_t)(l - 1) * 64,
                                          bn_gamma + (size_t)l * 64,
                                          bn_beta + (size_t)l * 64);
    }

    dense0_partial<<<512, 128>>>(dW0);
    dense0_reduce<<<32, 256>>>(db0, dbn_gamma, dbn_beta);
    head_kernel<<<4, 128>>>(dW1, db1, dbn_gamma, dbn_beta, W2, b2, out);
}